// round 1
// baseline (speedup 1.0000x reference)
#include <cuda_runtime.h>
#include <cuda_bf16.h>
#include <math.h>

// ---------------- constants ----------------
#define BNUM 64
#define NGRP 128
#define NPER 48
#define EPER 192
#define MAXN 64
#define MAXE 256
#define DIN 32
#define DD 128
#define MM 256
#define SS 64
#define TT 5
#define KK 3
#define VN 6144
#define VE 24576
#define INV_TEMP 10.0f
#define SINK_ITERS 10

// ---------------- scratch layout (floats) ----------------
#define SZ_ENC_N ((size_t)VN * 128)
#define SZ_ENC_E ((size_t)VE * 128)
#define SZ_NS ((size_t)VN * 768)
#define SZ_ES ((size_t)VE * 1536)
#define SZ_UN ((size_t)VN * 768)
#define SZ_UE ((size_t)VE * 1536)
#define SZ_TMPN ((size_t)VN * 256)
#define SZ_TMPE ((size_t)VE * 384)
#define SZ_HC ((size_t)VN * 128)
#define SZ_EC ((size_t)VE * 128)
#define SZ_FWD ((size_t)VE * 256)
#define SZ_AGG ((size_t)VN * 256)
#define SZ_TN ((size_t)NGRP * 64 * 64)
#define SZ_TE ((size_t)NGRP * 256 * 64)
#define SZ_PLN ((size_t)BNUM * 64 * 64)
#define SZ_PLE ((size_t)BNUM * 256 * 256)

#define OFF_ENC_N ((size_t)0)
#define OFF_ENC_E (OFF_ENC_N + SZ_ENC_N)
#define OFF_NS (OFF_ENC_E + SZ_ENC_E)
#define OFF_ES (OFF_NS + SZ_NS)
#define OFF_UN (OFF_ES + SZ_ES)
#define OFF_UE (OFF_UN + SZ_UN)
#define OFF_TMPN (OFF_UE + SZ_UE)
#define OFF_TMPE (OFF_TMPN + SZ_TMPN)
#define OFF_HC (OFF_TMPE + SZ_TMPE)
#define OFF_EC (OFF_HC + SZ_HC)
#define OFF_FWD (OFF_EC + SZ_EC)
#define OFF_BWD (OFF_FWD + SZ_FWD)
#define OFF_AGG (OFF_BWD + SZ_FWD)
#define OFF_TN (OFF_AGG + SZ_AGG)
#define OFF_TE (OFF_TN + SZ_TN)
#define OFF_PLN (OFF_TE + SZ_TE)
#define OFF_PLE (OFF_PLN + SZ_PLN)
#define SCRATCH_TOTAL (OFF_PLE + SZ_PLE)

__device__ float g_scratch[SCRATCH_TOTAL];

// ---------------- generic tiled SGEMM ----------------
// C[M,N] (+)= op(A[M,K]) @ B[K,N] (+bias) (relu)
// A row-major with stride lda; optional row-gather via a_rows.
// flags: 1 = accumulate into C, 2 = relu at end.
#define GBM 64
#define GBN 64
#define GBK 16

__global__ __launch_bounds__(256) void gemm_kernel(
    const float* __restrict__ A, int lda, const int* __restrict__ a_rows,
    const float* __restrict__ B, int ldb,
    const float* __restrict__ bias,
    float* __restrict__ C, int ldc,
    int Mdim, int Ndim, int Kdim, int flags)
{
    __shared__ float As[GBK][GBM];
    __shared__ float Bs[GBK][GBN];
    int block_row = blockIdx.y * GBM;
    int block_col = blockIdx.x * GBN;
    int tid = threadIdx.x;
    float acc[4][4];
#pragma unroll
    for (int i = 0; i < 4; i++)
#pragma unroll
        for (int j = 0; j < 4; j++) acc[i][j] = 0.f;

    int tr = (tid / 16) * 4;
    int tc = (tid % 16) * 4;

    for (int k0 = 0; k0 < Kdim; k0 += GBK) {
#pragma unroll
        for (int u = 0; u < 4; u++) {
            int idx = tid + u * 256;
            int m = idx / GBK;
            int k = idx % GBK;
            int gm = block_row + m;
            int gk = k0 + k;
            float v = 0.f;
            if (gm < Mdim && gk < Kdim) {
                int row = a_rows ? a_rows[gm] : gm;
                v = A[(size_t)row * lda + gk];
            }
            As[k][m] = v;
        }
#pragma unroll
        for (int u = 0; u < 4; u++) {
            int idx = tid + u * 256;
            int k = idx / GBN;
            int n = idx % GBN;
            int gk = k0 + k;
            int gn = block_col + n;
            float v = 0.f;
            if (gk < Kdim && gn < Ndim) v = B[(size_t)gk * ldb + gn];
            Bs[k][n] = v;
        }
        __syncthreads();
#pragma unroll
        for (int k = 0; k < GBK; k++) {
            float a0 = As[k][tr], a1 = As[k][tr + 1], a2 = As[k][tr + 2], a3 = As[k][tr + 3];
            float b0 = Bs[k][tc], b1 = Bs[k][tc + 1], b2 = Bs[k][tc + 2], b3 = Bs[k][tc + 3];
            acc[0][0] += a0 * b0; acc[0][1] += a0 * b1; acc[0][2] += a0 * b2; acc[0][3] += a0 * b3;
            acc[1][0] += a1 * b0; acc[1][1] += a1 * b1; acc[1][2] += a1 * b2; acc[1][3] += a1 * b3;
            acc[2][0] += a2 * b0; acc[2][1] += a2 * b1; acc[2][2] += a2 * b2; acc[2][3] += a2 * b3;
            acc[3][0] += a3 * b0; acc[3][1] += a3 * b1; acc[3][2] += a3 * b2; acc[3][3] += a3 * b3;
        }
        __syncthreads();
    }

#pragma unroll
    for (int i = 0; i < 4; i++) {
        int r = block_row + tr + i;
        if (r >= Mdim) continue;
#pragma unroll
        for (int j = 0; j < 4; j++) {
            int c = block_col + tc + j;
            if (c >= Ndim) continue;
            float v = acc[i][j];
            size_t off = (size_t)r * ldc + c;
            if (flags & 1) v += C[off];
            if (bias) v += bias[c];
            if (flags & 2) v = fmaxf(v, 0.f);
            C[off] = v;
        }
    }
}

// ---------------- misc elementwise ----------------
__global__ void zero_kernel(float* __restrict__ p, size_t n) {
    size_t i = (size_t)blockIdx.x * blockDim.x + threadIdx.x;
    size_t stride = (size_t)gridDim.x * blockDim.x;
    for (; i < n; i += stride) p[i] = 0.f;
}

__global__ void exp_kernel(float* __restrict__ p, size_t n) {
    size_t i = (size_t)blockIdx.x * blockDim.x + threadIdx.x;
    size_t stride = (size_t)gridDim.x * blockDim.x;
    for (; i < n; i += stride) p[i] = expf(p[i]);
}

// ---------------- message aggregation scatter ----------------
__global__ void scatter_add_kernel(const float* __restrict__ fwd, const float* __restrict__ bwd,
                                   const int* __restrict__ from_idx, const int* __restrict__ to_idx,
                                   float* __restrict__ agg)
{
    size_t i = (size_t)blockIdx.x * blockDim.x + threadIdx.x;
    if (i >= (size_t)VE * 256) return;
    int e = (int)(i >> 8);
    int c = (int)(i & 255);
    atomicAdd(&agg[(size_t)to_idx[e] * 256 + c], fwd[i]);
    atomicAdd(&agg[(size_t)from_idx[e] * 256 + c], bwd[i]);
}

// ---------------- transport MLP (fdim -> 64 -> 64, pad rows zero) ----------------
__global__ void transport_mlp_kernel(const float* __restrict__ upd, int ld, int foff, int fdim,
                                     const float* __restrict__ W1, const float* __restrict__ b1,
                                     const float* __restrict__ W2, const float* __restrict__ b2,
                                     float* __restrict__ tout, int maxr, int nreal)
{
    int i = blockIdx.x;   // 0..maxr-1
    int g = blockIdx.y;   // 0..NGRP-1
    int j = threadIdx.x;  // 0..63
    size_t outoff = ((size_t)g * maxr + i) * 64 + j;
    if (i >= nreal) { tout[outoff] = 0.f; return; }
    __shared__ float f[256];
    __shared__ float hid[64];
    const float* frow = upd + ((size_t)g * nreal + i) * ld + foff;
    for (int k = j; k < fdim; k += 64) f[k] = frow[k];
    __syncthreads();
    float h = b1[j];
    for (int k = 0; k < fdim; k++) h += f[k] * W1[k * 64 + j];
    hid[j] = fmaxf(h, 0.f);
    __syncthreads();
    float o = b2[j];
#pragma unroll
    for (int k = 0; k < 64; k++) o += hid[k] * W2[k * 64 + j];
    tout[outoff] = o;
}

// ---------------- la = (tq @ tc^T) / TEMP ----------------
__global__ void la_kernel(const float* __restrict__ t, float* __restrict__ la, int maxr)
{
    __shared__ float Tq[16][65];
    __shared__ float Tc[16][65];
    int b = blockIdx.z;
    int q0 = blockIdx.y * 16;
    int c0 = blockIdx.x * 16;
    const float* tq = t + (size_t)(2 * b) * maxr * 64;
    const float* tc = t + (size_t)(2 * b + 1) * maxr * 64;
    int ty = threadIdx.y, tx = threadIdx.x;
    int lin = ty * 16 + tx;
#pragma unroll
    for (int u = 0; u < 4; u++) {
        int idx = lin + u * 256;
        int r = idx / 64, k = idx % 64;
        Tq[r][k] = tq[(size_t)(q0 + r) * 64 + k];
        Tc[r][k] = tc[(size_t)(c0 + r) * 64 + k];
    }
    __syncthreads();
    float s = 0.f;
#pragma unroll
    for (int k = 0; k < 64; k++) s += Tq[ty][k] * Tc[tx][k];
    la[((size_t)b * maxr + q0 + ty) * maxr + c0 + tx] = s * INV_TEMP;
}

// ---------------- Sinkhorn normalizations ----------------
__global__ void sink_row_kernel(float* __restrict__ la, int maxr)
{
    __shared__ float red[256];
    int row = blockIdx.x;
    float* base = la + (size_t)row * maxr;
    int t = threadIdx.x;
    float v = base[t];
    red[t] = v;
    __syncthreads();
    for (int s = maxr >> 1; s > 0; s >>= 1) {
        if (t < s) red[t] = fmaxf(red[t], red[t + s]);
        __syncthreads();
    }
    float m = red[0];
    __syncthreads();
    red[t] = expf(v - m);
    __syncthreads();
    for (int s = maxr >> 1; s > 0; s >>= 1) {
        if (t < s) red[t] += red[t + s];
        __syncthreads();
    }
    float lse = m + logf(red[0]);
    base[t] = v - lse;
}

__global__ void sink_col_kernel(float* __restrict__ la, int maxr)
{
    // block (32 cols, 8 q-threads)
    __shared__ float red[8][32];
    int b = blockIdx.y;
    int c = blockIdx.x * 32 + threadIdx.x;
    int tq = threadIdx.y;
    int tx = threadIdx.x;
    float* base = la + (size_t)b * maxr * maxr + c;
    float m = -INFINITY;
    for (int q = tq; q < maxr; q += 8) m = fmaxf(m, base[(size_t)q * maxr]);
    red[tq][tx] = m;
    __syncthreads();
    for (int s = 4; s > 0; s >>= 1) {
        if (tq < s) red[tq][tx] = fmaxf(red[tq][tx], red[tq + s][tx]);
        __syncthreads();
    }
    m = red[0][tx];
    __syncthreads();
    float sum = 0.f;
    for (int q = tq; q < maxr; q += 8) sum += expf(base[(size_t)q * maxr] - m);
    red[tq][tx] = sum;
    __syncthreads();
    for (int s = 4; s > 0; s >>= 1) {
        if (tq < s) red[tq][tx] += red[tq + s][tx];
        __syncthreads();
    }
    float lse = m + logf(red[0][tx]);
    for (int q = tq; q < maxr; q += 8) base[(size_t)q * maxr] -= lse;
}

// ---------------- plan apply: store rows = plan(^T) @ feats ----------------
// grid.z = 2*b + mode ; mode 0: qi (P normal, feats from group 2b+1, out group 2b)
//                       mode 1: ci (P transposed, feats from group 2b, out group 2b+1)
__global__ __launch_bounds__(256) void trans_apply_kernel(
    const float* __restrict__ plan, const float* __restrict__ upd,
    float* __restrict__ store, int maxr, int nreal, int ld, int coff)
{
    __shared__ float Ps[GBK][GBM];
    __shared__ float Fs[GBK][GBN];
    int z = blockIdx.z;
    int b = z >> 1;
    int mode = z & 1;
    const float* P = plan + (size_t)b * maxr * maxr;
    int fgrp = 2 * b + (mode ? 0 : 1);
    int ogrp = 2 * b + mode;
    const float* F = upd + (size_t)fgrp * nreal * ld + coff;
    float* C = store + (size_t)ogrp * nreal * ld + coff;
    int ncols = ld - coff;
    int block_row = blockIdx.y * GBM;
    int block_col = blockIdx.x * GBN;
    int tid = threadIdx.x;
    float acc[4][4];
#pragma unroll
    for (int i = 0; i < 4; i++)
#pragma unroll
        for (int j = 0; j < 4; j++) acc[i][j] = 0.f;
    int tr = (tid / 16) * 4;
    int tc = (tid % 16) * 4;

    for (int k0 = 0; k0 < nreal; k0 += GBK) {
#pragma unroll
        for (int u = 0; u < 4; u++) {
            int idx = tid + u * 256;
            int m = idx / GBK;
            int k = idx % GBK;
            int gr = block_row + m;
            int gk = k0 + k;
            float v = 0.f;
            if (gr < nreal && gk < nreal)
                v = mode ? P[(size_t)gk * maxr + gr] : P[(size_t)gr * maxr + gk];
            Ps[k][m] = v;
        }
#pragma unroll
        for (int u = 0; u < 4; u++) {
            int idx = tid + u * 256;
            int k = idx / GBN;
            int n = idx % GBN;
            int gk = k0 + k;
            int gn = block_col + n;
            float v = 0.f;
            if (gk < nreal && gn < ncols) v = F[(size_t)gk * ld + gn];
            Fs[k][n] = v;
        }
        __syncthreads();
#pragma unroll
        for (int k = 0; k < GBK; k++) {
            float a0 = Ps[k][tr], a1 = Ps[k][tr + 1], a2 = Ps[k][tr + 2], a3 = Ps[k][tr + 3];
            float b0 = Fs[k][tc], b1 = Fs[k][tc + 1], b2 = Fs[k][tc + 2], b3 = Fs[k][tc + 3];
            acc[0][0] += a0 * b0; acc[0][1] += a0 * b1; acc[0][2] += a0 * b2; acc[0][3] += a0 * b3;
            acc[1][0] += a1 * b0; acc[1][1] += a1 * b1; acc[1][2] += a1 * b2; acc[1][3] += a1 * b3;
            acc[2][0] += a2 * b0; acc[2][1] += a2 * b1; acc[2][2] += a2 * b2; acc[2][3] += a2 * b3;
            acc[3][0] += a3 * b0; acc[3][1] += a3 * b1; acc[3][2] += a3 * b2; acc[3][3] += a3 * b3;
        }
        __syncthreads();
    }

#pragma unroll
    for (int i = 0; i < 4; i++) {
        int r = block_row + tr + i;
        if (r >= nreal) continue;
#pragma unroll
        for (int j = 0; j < 4; j++) {
            int c = block_col + tc + j;
            if (c >= ncols) continue;
            C[(size_t)r * ld + c] = acc[i][j];
        }
    }
}

// ---------------- score ----------------
__global__ void score_kernel(const float* __restrict__ upd_node, const float* __restrict__ plan,
                             float* __restrict__ out)
{
    int b = blockIdx.x;
    int t = threadIdx.x;  // 0..127 (d)
    __shared__ float P[64][64];
    __shared__ float FC[48][128];
    __shared__ float red[128];
    for (int idx = t; idx < 64 * 64; idx += 128)
        P[idx / 64][idx % 64] = plan[(size_t)b * 4096 + idx];
    for (int idx = t; idx < 48 * 128; idx += 128) {
        int c = idx / 128, d = idx % 128;
        FC[c][d] = upd_node[((size_t)(2 * b + 1) * 48 + c) * 768 + 640 + d];
    }
    __syncthreads();
    float acc = 0.f;
    for (int q = 0; q < 64; q++) {
        float s = 0.f;
#pragma unroll 8
        for (int c = 0; c < 48; c++) s += P[q][c] * FC[c][t];
        float fq = 0.f;
        if (q < 48) fq = upd_node[((size_t)(2 * b) * 48 + q) * 768 + 640 + t];
        acc += fmaxf(fq - s, 0.f);
    }
    red[t] = acc;
    __syncthreads();
    for (int s2 = 64; s2 > 0; s2 >>= 1) {
        if (t < s2) red[t] += red[t + s2];
        __syncthreads();
    }
    if (t == 0) out[b] = -red[0];
}

// ---------------- host helpers ----------------
static void gemm(const float* A, int lda, const int* ar, const float* B, int ldb,
                 const float* bias, float* C, int ldc, int M, int N, int K, int flags)
{
    dim3 g((N + GBN - 1) / GBN, (M + GBM - 1) / GBM);
    gemm_kernel<<<g, 256>>>(A, lda, ar, B, ldb, bias, C, ldc, M, N, K, flags);
}

static void zero_buf(float* p, size_t n)
{
    int grid = (int)((n + 255) / 256);
    if (grid > 8192) grid = 8192;
    zero_kernel<<<grid, 256>>>(p, n);
}

extern "C" void kernel_launch(void* const* d_in, const int* in_sizes, int n_in,
                              void* d_out, int out_size)
{
    const float* node_features = (const float*)d_in[0];
    const float* edge_features = (const float*)d_in[1];
    const int* from_idx = (const int*)d_in[2];
    const int* to_idx = (const int*)d_in[3];
    const float* enc_node_W = (const float*)d_in[4];
    const float* enc_node_b = (const float*)d_in[5];
    const float* enc_edge_W = (const float*)d_in[6];
    const float* enc_edge_b = (const float*)d_in[7];
    const float* ni_W1 = (const float*)d_in[8];
    const float* ni_b1 = (const float*)d_in[9];
    const float* ni_W2 = (const float*)d_in[10];
    const float* ni_b2 = (const float*)d_in[11];
    const float* ei_W1 = (const float*)d_in[12];
    const float* ei_b1 = (const float*)d_in[13];
    const float* ei_W2 = (const float*)d_in[14];
    const float* ei_b2 = (const float*)d_in[15];
    const float* msg_W = (const float*)d_in[16];
    const float* msg_b = (const float*)d_in[17];
    const float* nu_W1 = (const float*)d_in[18];
    const float* nu_b1 = (const float*)d_in[19];
    const float* nu_W2 = (const float*)d_in[20];
    const float* nu_b2 = (const float*)d_in[21];
    const float* ns_W1 = (const float*)d_in[22];
    const float* ns_b1 = (const float*)d_in[23];
    const float* ns_W2 = (const float*)d_in[24];
    const float* ns_b2 = (const float*)d_in[25];
    const float* es_W1 = (const float*)d_in[26];
    const float* es_b1 = (const float*)d_in[27];
    const float* es_W2 = (const float*)d_in[28];
    const float* es_b2 = (const float*)d_in[29];

    float* S = nullptr;
    cudaGetSymbolAddress((void**)&S, g_scratch);

    float* enc_n = S + OFF_ENC_N;
    float* enc_e = S + OFF_ENC_E;
    float* node_store = S + OFF_NS;
    float* edge_store = S + OFF_ES;
    float* UN = S + OFF_UN;
    float* UE = S + OFF_UE;
    float* tmpN = S + OFF_TMPN;
    float* tmpE = S + OFF_TMPE;
    float* hcomb = S + OFF_HC;
    float* ecomb = S + OFF_EC;
    float* fwd = S + OFF_FWD;
    float* bwd = S + OFF_BWD;
    float* agg = S + OFF_AGG;
    float* TN = S + OFF_TN;
    float* TE = S + OFF_TE;
    float* PLN = S + OFF_PLN;
    float* PLE = S + OFF_PLE;

    // stores start at zero
    zero_buf(node_store, SZ_NS);
    zero_buf(edge_store, SZ_ES);

    // encoders
    gemm(node_features, DIN, nullptr, enc_node_W, 128, enc_node_b, enc_n, 128, VN, 128, DIN, 0);
    gemm(edge_features, DIN, nullptr, enc_edge_W, 128, enc_edge_b, enc_e, 128, VE, 128, DIN, 0);

    for (int k = 0; k < KK; k++) {
        for (int p = 1; p <= TT; p++) {
            const float* hptr = (p == 1) ? enc_n : (UN + (size_t)(p - 1) * 128);
            int hlda = (p == 1) ? 128 : 768;

            // h_comb = mlp2([h | node_store slice], ni)
            gemm(hptr, hlda, nullptr, ni_W1, 256, nullptr, tmpN, 256, VN, 256, 128, 0);
            gemm(node_store + (size_t)(p - 1) * 128, 768, nullptr, ni_W1 + 128 * 256, 256,
                 ni_b1, tmpN, 256, VN, 256, 128, 1 | 2);
            gemm(tmpN, 256, nullptr, ni_W2, 128, ni_b2, hcomb, 128, VN, 128, 256, 0);

            // e_comb = mlp2([enc_e | edge_store slice], ei)
            gemm(enc_e, 128, nullptr, ei_W1, 384, nullptr, tmpE, 384, VE, 384, 128, 0);
            gemm(edge_store + (size_t)(p - 1) * 256, 1536, nullptr, ei_W1 + 128 * 384, 384,
                 ei_b1, tmpE, 384, VE, 384, 256, 1 | 2);
            gemm(tmpE, 384, nullptr, ei_W2, 128, ei_b2, ecomb, 128, VE, 128, 384, 0);

            // fwd/bwd messages
            gemm(hcomb, 128, from_idx, msg_W, 256, nullptr, fwd, 256, VE, 256, 128, 0);
            gemm(hcomb, 128, to_idx, msg_W + 128 * 256, 256, nullptr, fwd, 256, VE, 256, 128, 1);
            gemm(ecomb, 128, nullptr, msg_W + 256 * 256, 256, msg_b, fwd, 256, VE, 256, 128, 1);
            gemm(hcomb, 128, to_idx, msg_W, 256, nullptr, bwd, 256, VE, 256, 128, 0);
            gemm(hcomb, 128, from_idx, msg_W + 128 * 256, 256, nullptr, bwd, 256, VE, 256, 128, 1);
            gemm(ecomb, 128, nullptr, msg_W + 256 * 256, 256, msg_b, bwd, 256, VE, 256, 128, 1);

            // aggregate
            zero_buf(agg, SZ_AGG);
            {
                size_t tot = (size_t)VE * 256;
                int grid = (int)((tot + 255) / 256);
                scatter_add_kernel<<<grid, 256>>>(fwd, bwd, from_idx, to_idx, agg);
            }

            // h_new = mlp2([h_comb | agg], nu) -> upd_node slot p
            gemm(hcomb, 128, nullptr, nu_W1, 256, nullptr, tmpN, 256, VN, 256, 128, 0);
            gemm(agg, 256, nullptr, nu_W1 + 128 * 256, 256, nu_b1, tmpN, 256, VN, 256, 256, 1 | 2);
            gemm(tmpN, 256, nullptr, nu_W2, 128, nu_b2, UN + (size_t)p * 128, 768, VN, 128, 256, 0);

            // msgs = fwd2 + bwd2 -> upd_edge slot p
            const float* hn = UN + (size_t)p * 128;
            float* Cm = UE + (size_t)p * 256;
            gemm(hn, 768, from_idx, msg_W, 256, nullptr, Cm, 1536, VE, 256, 128, 0);
            gemm(hn, 768, to_idx, msg_W + 128 * 256, 256, nullptr, Cm, 1536, VE, 256, 128, 1);
            gemm(ecomb, 128, nullptr, msg_W + 256 * 256, 256, msg_b, Cm, 1536, VE, 256, 128, 1);
            gemm(hn, 768, to_idx, msg_W, 256, nullptr, Cm, 1536, VE, 256, 128, 1);
            gemm(hn, 768, from_idx, msg_W + 128 * 256, 256, nullptr, Cm, 1536, VE, 256, 128, 1);
            gemm(ecomb, 128, nullptr, msg_W + 256 * 256, 256, msg_b, Cm, 1536, VE, 256, 128, 1);
        }

        // ----- node transport -----
        transport_mlp_kernel<<<dim3(MAXN, NGRP), 64>>>(UN, 768, 640, 128, ns_W1, ns_b1,
                                                       ns_W2, ns_b2, TN, MAXN, NPER);
        la_kernel<<<dim3(4, 4, BNUM), dim3(16, 16)>>>(TN, PLN, MAXN);
        for (int it = 0; it < SINK_ITERS; it++) {
            sink_row_kernel<<<BNUM * MAXN, MAXN>>>(PLN, MAXN);
            sink_col_kernel<<<dim3(MAXN / 32, BNUM), dim3(32, 8)>>>(PLN, MAXN);
        }
        exp_kernel<<<1024, 256>>>(PLN, SZ_PLN);
        zero_buf(node_store, SZ_NS);
        trans_apply_kernel<<<dim3(10, 1, NGRP), 256>>>(PLN, UN, node_store, MAXN, NPER, 768, 128);

        // ----- edge transport -----
        transport_mlp_kernel<<<dim3(MAXE, NGRP), 64>>>(UE, 1536, 1280, 256, es_W1, es_b1,
                                                       es_W2, es_b2, TE, MAXE, EPER);
        la_kernel<<<dim3(16, 16, BNUM), dim3(16, 16)>>>(TE, PLE, MAXE);
        for (int it = 0; it < SINK_ITERS; it++) {
            sink_row_kernel<<<BNUM * MAXE, MAXE>>>(PLE, MAXE);
            sink_col_kernel<<<dim3(MAXE / 32, BNUM), dim3(32, 8)>>>(PLE, MAXE);
        }
        exp_kernel<<<8192, 256>>>(PLE, SZ_PLE);
        zero_buf(edge_store, SZ_ES);
        trans_apply_kernel<<<dim3(20, 3, NGRP), 256>>>(PLE, UE, edge_store, MAXE, EPER, 1536, 256);
    }

    // ----- score -----
    score_kernel<<<BNUM, 128>>>(UN, PLN, (float*)d_out);
}

// round 2
// speedup vs baseline: 1.7833x; 1.7833x over previous
#include <cuda_runtime.h>
#include <cuda_bf16.h>
#include <math.h>

// ---------------- constants ----------------
#define BNUM 64
#define NGRP 128
#define NPER 48
#define EPER 192
#define MAXN 64
#define MAXE 256
#define DIN 32
#define TT 5
#define KK 3
#define VN 6144
#define VE 24576
#define INV_TEMP 10.0f
#define SINK_ITERS 10

// ---------------- scratch layout (floats) ----------------
#define SZ_ENC_N ((size_t)VN * 128)
#define SZ_ENC_E ((size_t)VE * 128)
#define SZ_NS ((size_t)VN * 768)
#define SZ_ES ((size_t)VE * 1536)
#define SZ_UN ((size_t)VN * 768)
#define SZ_UE ((size_t)VE * 1536)
#define SZ_TMPN ((size_t)VN * 256)
#define SZ_TMPE ((size_t)VE * 384)
#define SZ_HC ((size_t)VN * 128)
#define SZ_EC ((size_t)VE * 128)
#define SZ_FWD ((size_t)VE * 256)
#define SZ_AGG ((size_t)VN * 256)
#define SZ_TN ((size_t)NGRP * 64 * 64)
#define SZ_TE ((size_t)NGRP * 256 * 64)
#define SZ_PLN ((size_t)BNUM * 64 * 64)
#define SZ_PLE ((size_t)BNUM * 256 * 256)
#define SZ_EWC ((size_t)VE * 256)
#define SZ_WAB ((size_t)128 * 256)

#define OFF_ENC_N ((size_t)0)
#define OFF_ENC_E (OFF_ENC_N + SZ_ENC_N)
#define OFF_NS (OFF_ENC_E + SZ_ENC_E)
#define OFF_ES (OFF_NS + SZ_NS)
#define OFF_UN (OFF_ES + SZ_ES)
#define OFF_UE (OFF_UN + SZ_UN)
#define OFF_TMPN (OFF_UE + SZ_UE)
#define OFF_TMPE (OFF_TMPN + SZ_TMPN)
#define OFF_HC (OFF_TMPE + SZ_TMPE)
#define OFF_EC (OFF_HC + SZ_HC)
#define OFF_FWD (OFF_EC + SZ_EC)
#define OFF_BWD (OFF_FWD + SZ_FWD)
#define OFF_AGG (OFF_BWD + SZ_FWD)
#define OFF_TN (OFF_AGG + SZ_AGG)
#define OFF_TE (OFF_TN + SZ_TN)
#define OFF_PLN (OFF_TE + SZ_TE)
#define OFF_PLE (OFF_PLN + SZ_PLN)
#define OFF_EWC (OFF_PLE + SZ_PLE)
#define OFF_WAB (OFF_EWC + SZ_EWC)
#define SCRATCH_TOTAL (OFF_WAB + SZ_WAB)

__device__ float g_scratch[SCRATCH_TOTAL];

// =====================================================================
// gemm3: C[M,N] = concat_K(A0|A1|A2) @ B + bias + cin_scale*Cin, opt relu
// Requirements: M%128==0, N%128==0, K%16==0, ldb==N, all float4-aligned.
// Segments: [0,kb1) -> A0, [kb1,kb2) -> A1, [kb2,K) -> A2. Each segment has
// optional row-gather index array.
// =====================================================================
#define TBM 128
#define TBN 128
#define TBK 16

__global__ __launch_bounds__(256) void gemm3_kernel(
    const float* __restrict__ A0, int lda0, const int* __restrict__ r0,
    const float* __restrict__ A1, int lda1, const int* __restrict__ r1,
    const float* __restrict__ A2, int lda2, const int* __restrict__ r2,
    int kb1, int kb2,
    const float* __restrict__ B,
    const float* __restrict__ bias,
    const float* __restrict__ Cin, int ldcin, float cin_scale,
    float* __restrict__ C, int ldc,
    int Mdim, int Ndim, int Kdim, int relu)
{
    __shared__ __align__(16) float As[TBK][TBM];
    __shared__ __align__(16) float Bs[TBK][TBN];

    const int tid = threadIdx.x;
    const int row0 = blockIdx.y * TBM;
    const int col0 = blockIdx.x * TBN;
    const int tr = (tid >> 4) << 3;   // 0..120
    const int tc = (tid & 15) << 3;   // 0..120

    float acc[8][8];
#pragma unroll
    for (int i = 0; i < 8; i++)
#pragma unroll
        for (int j = 0; j < 8; j++) acc[i][j] = 0.f;

    for (int k0 = 0; k0 < Kdim; k0 += TBK) {
        const float* Ap;
        int lda;
        const int* rows;
        int kloc;
        if (k0 < kb1) { Ap = A0; lda = lda0; rows = r0; kloc = k0; }
        else if (k0 < kb2) { Ap = A1; lda = lda1; rows = r1; kloc = k0 - kb1; }
        else { Ap = A2; lda = lda2; rows = r2; kloc = k0 - kb2; }

        // A fill: 512 float4 loads (128 rows x 16 k)
#pragma unroll
        for (int u = 0; u < 2; u++) {
            int idx = tid + u * 256;
            int m = idx >> 2;
            int kj = (idx & 3) << 2;
            int gm = row0 + m;
            int row = rows ? __ldg(&rows[gm]) : gm;
            float4 v = *(const float4*)(Ap + (size_t)row * lda + kloc + kj);
            As[kj + 0][m] = v.x;
            As[kj + 1][m] = v.y;
            As[kj + 2][m] = v.z;
            As[kj + 3][m] = v.w;
        }
        // B fill
#pragma unroll
        for (int u = 0; u < 2; u++) {
            int idx = tid + u * 256;
            int kk = idx >> 5;
            int n4 = (idx & 31) << 2;
            *(float4*)&Bs[kk][n4] = *(const float4*)(B + (size_t)(k0 + kk) * Ndim + col0 + n4);
        }
        __syncthreads();

#pragma unroll
        for (int kk = 0; kk < TBK; kk++) {
            float a[8], b[8];
            *(float4*)a = *(const float4*)&As[kk][tr];
            *(float4*)(a + 4) = *(const float4*)&As[kk][tr + 4];
            *(float4*)b = *(const float4*)&Bs[kk][tc];
            *(float4*)(b + 4) = *(const float4*)&Bs[kk][tc + 4];
#pragma unroll
            for (int i = 0; i < 8; i++)
#pragma unroll
                for (int j = 0; j < 8; j++)
                    acc[i][j] += a[i] * b[j];
        }
        __syncthreads();
    }

    // epilogue
#pragma unroll
    for (int i = 0; i < 8; i++) {
        int r = row0 + tr + i;
        float* crow = C + (size_t)r * ldc + col0 + tc;
        const float* cinrow = Cin ? (Cin + (size_t)r * ldcin + col0 + tc) : nullptr;
#pragma unroll
        for (int j = 0; j < 8; j++) {
            float v = acc[i][j];
            if (bias) v += bias[col0 + tc + j];
            if (cinrow) v += cin_scale * cinrow[j];
            if (relu) v = fmaxf(v, 0.f);
            crow[j] = v;
        }
    }
}

// ---------------- misc elementwise ----------------
__global__ void zero_kernel(float* __restrict__ p, size_t n) {
    size_t i = (size_t)blockIdx.x * blockDim.x + threadIdx.x;
    size_t stride = (size_t)gridDim.x * blockDim.x;
    for (; i < n; i += stride) p[i] = 0.f;
}

__global__ void exp_kernel(float* __restrict__ p, size_t n) {
    size_t i = (size_t)blockIdx.x * blockDim.x + threadIdx.x;
    size_t stride = (size_t)gridDim.x * blockDim.x;
    for (; i < n; i += stride) p[i] = expf(p[i]);
}

__global__ void wab_kernel(const float* __restrict__ msgW, float* __restrict__ wab) {
    int i = blockIdx.x * blockDim.x + threadIdx.x;  // 128*256
    if (i < 128 * 256) wab[i] = msgW[i] + msgW[128 * 256 + i];
}

// sumsd[e][0:128] = hn[from[e]] + hn[to[e]]  (hn stride 768), float4
__global__ void sumsd_kernel(const float* __restrict__ hn, const int* __restrict__ from_idx,
                             const int* __restrict__ to_idx, float* __restrict__ out)
{
    int i = blockIdx.x * blockDim.x + threadIdx.x;  // VE*32
    if (i >= VE * 32) return;
    int e = i >> 5;
    int c4 = (i & 31) << 2;
    const float4 a = *(const float4*)(hn + (size_t)from_idx[e] * 768 + c4);
    const float4 b = *(const float4*)(hn + (size_t)to_idx[e] * 768 + c4);
    float4 o;
    o.x = a.x + b.x; o.y = a.y + b.y; o.z = a.z + b.z; o.w = a.w + b.w;
    *(float4*)(out + (size_t)e * 128 + c4) = o;
}

// ---------------- message aggregation scatter ----------------
__global__ void scatter_add_kernel(const float* __restrict__ fwd, const float* __restrict__ bwd,
                                   const int* __restrict__ from_idx, const int* __restrict__ to_idx,
                                   float* __restrict__ agg)
{
    size_t i = (size_t)blockIdx.x * blockDim.x + threadIdx.x;
    if (i >= (size_t)VE * 256) return;
    int e = (int)(i >> 8);
    int c = (int)(i & 255);
    atomicAdd(&agg[(size_t)to_idx[e] * 256 + c], fwd[i]);
    atomicAdd(&agg[(size_t)from_idx[e] * 256 + c], bwd[i]);
}

// ---------------- transport MLP (fdim -> 64 -> 64, pad rows zero) ----------------
__global__ void transport_mlp_kernel(const float* __restrict__ upd, int ld, int foff, int fdim,
                                     const float* __restrict__ W1, const float* __restrict__ b1,
                                     const float* __restrict__ W2, const float* __restrict__ b2,
                                     float* __restrict__ tout, int maxr, int nreal)
{
    int i = blockIdx.x;
    int g = blockIdx.y;
    int j = threadIdx.x;
    size_t outoff = ((size_t)g * maxr + i) * 64 + j;
    if (i >= nreal) { tout[outoff] = 0.f; return; }
    __shared__ float f[256];
    __shared__ float hid[64];
    const float* frow = upd + ((size_t)g * nreal + i) * ld + foff;
    for (int k = j; k < fdim; k += 64) f[k] = frow[k];
    __syncthreads();
    float h = b1[j];
    for (int k = 0; k < fdim; k++) h += f[k] * W1[k * 64 + j];
    hid[j] = fmaxf(h, 0.f);
    __syncthreads();
    float o = b2[j];
#pragma unroll
    for (int k = 0; k < 64; k++) o += hid[k] * W2[k * 64 + j];
    tout[outoff] = o;
}

// ---------------- la = (tq @ tc^T) / TEMP ----------------
__global__ void la_kernel(const float* __restrict__ t, float* __restrict__ la, int maxr)
{
    __shared__ float Tq[16][65];
    __shared__ float Tc[16][65];
    int b = blockIdx.z;
    int q0 = blockIdx.y * 16;
    int c0 = blockIdx.x * 16;
    const float* tq = t + (size_t)(2 * b) * maxr * 64;
    const float* tc = t + (size_t)(2 * b + 1) * maxr * 64;
    int ty = threadIdx.y, tx = threadIdx.x;
    int lin = ty * 16 + tx;
#pragma unroll
    for (int u = 0; u < 4; u++) {
        int idx = lin + u * 256;
        int r = idx / 64, k = idx % 64;
        Tq[r][k] = tq[(size_t)(q0 + r) * 64 + k];
        Tc[r][k] = tc[(size_t)(c0 + r) * 64 + k];
    }
    __syncthreads();
    float s = 0.f;
#pragma unroll
    for (int k = 0; k < 64; k++) s += Tq[ty][k] * Tc[tx][k];
    la[((size_t)b * maxr + q0 + ty) * maxr + c0 + tx] = s * INV_TEMP;
}

// ---------------- Sinkhorn normalizations ----------------
__global__ void sink_row_kernel(float* __restrict__ la, int maxr)
{
    __shared__ float red[256];
    int row = blockIdx.x;
    float* base = la + (size_t)row * maxr;
    int t = threadIdx.x;
    float v = base[t];
    red[t] = v;
    __syncthreads();
    for (int s = maxr >> 1; s > 0; s >>= 1) {
        if (t < s) red[t] = fmaxf(red[t], red[t + s]);
        __syncthreads();
    }
    float m = red[0];
    __syncthreads();
    red[t] = expf(v - m);
    __syncthreads();
    for (int s = maxr >> 1; s > 0; s >>= 1) {
        if (t < s) red[t] += red[t + s];
        __syncthreads();
    }
    float lse = m + logf(red[0]);
    base[t] = v - lse;
}

__global__ void sink_col_kernel(float* __restrict__ la, int maxr)
{
    __shared__ float red[8][32];
    int b = blockIdx.y;
    int c = blockIdx.x * 32 + threadIdx.x;
    int tq = threadIdx.y;
    int tx = threadIdx.x;
    float* base = la + (size_t)b * maxr * maxr + c;
    float m = -INFINITY;
    for (int q = tq; q < maxr; q += 8) m = fmaxf(m, base[(size_t)q * maxr]);
    red[tq][tx] = m;
    __syncthreads();
    for (int s = 4; s > 0; s >>= 1) {
        if (tq < s) red[tq][tx] = fmaxf(red[tq][tx], red[tq + s][tx]);
        __syncthreads();
    }
    m = red[0][tx];
    __syncthreads();
    float sum = 0.f;
    for (int q = tq; q < maxr; q += 8) sum += expf(base[(size_t)q * maxr] - m);
    red[tq][tx] = sum;
    __syncthreads();
    for (int s = 4; s > 0; s >>= 1) {
        if (tq < s) red[tq][tx] += red[tq + s][tx];
        __syncthreads();
    }
    float lse = m + logf(red[0][tx]);
    for (int q = tq; q < maxr; q += 8) base[(size_t)q * maxr] -= lse;
}

// ---------------- plan apply ----------------
#define GBM 64
#define GBN 64
#define GBK 16
__global__ __launch_bounds__(256) void trans_apply_kernel(
    const float* __restrict__ plan, const float* __restrict__ upd,
    float* __restrict__ store, int maxr, int nreal, int ld, int coff)
{
    __shared__ float Ps[GBK][GBM];
    __shared__ float Fs[GBK][GBN];
    int z = blockIdx.z;
    int b = z >> 1;
    int mode = z & 1;
    const float* P = plan + (size_t)b * maxr * maxr;
    int fgrp = 2 * b + (mode ? 0 : 1);
    int ogrp = 2 * b + mode;
    const float* F = upd + (size_t)fgrp * nreal * ld + coff;
    float* C = store + (size_t)ogrp * nreal * ld + coff;
    int ncols = ld - coff;
    int block_row = blockIdx.y * GBM;
    int block_col = blockIdx.x * GBN;
    int tid = threadIdx.x;
    float acc[4][4];
#pragma unroll
    for (int i = 0; i < 4; i++)
#pragma unroll
        for (int j = 0; j < 4; j++) acc[i][j] = 0.f;
    int tr = (tid / 16) * 4;
    int tc = (tid % 16) * 4;

    for (int k0 = 0; k0 < nreal; k0 += GBK) {
#pragma unroll
        for (int u = 0; u < 4; u++) {
            int idx = tid + u * 256;
            int m = idx / GBK;
            int k = idx % GBK;
            int gr = block_row + m;
            int gk = k0 + k;
            float v = 0.f;
            if (gr < nreal && gk < nreal)
                v = mode ? P[(size_t)gk * maxr + gr] : P[(size_t)gr * maxr + gk];
            Ps[k][m] = v;
        }
#pragma unroll
        for (int u = 0; u < 4; u++) {
            int idx = tid + u * 256;
            int k = idx / GBN;
            int n = idx % GBN;
            int gk = k0 + k;
            int gn = block_col + n;
            float v = 0.f;
            if (gk < nreal && gn < ncols) v = F[(size_t)gk * ld + gn];
            Fs[k][n] = v;
        }
        __syncthreads();
#pragma unroll
        for (int k = 0; k < GBK; k++) {
            float a0 = Ps[k][tr], a1 = Ps[k][tr + 1], a2 = Ps[k][tr + 2], a3 = Ps[k][tr + 3];
            float b0 = Fs[k][tc], b1 = Fs[k][tc + 1], b2 = Fs[k][tc + 2], b3 = Fs[k][tc + 3];
            acc[0][0] += a0 * b0; acc[0][1] += a0 * b1; acc[0][2] += a0 * b2; acc[0][3] += a0 * b3;
            acc[1][0] += a1 * b0; acc[1][1] += a1 * b1; acc[1][2] += a1 * b2; acc[1][3] += a1 * b3;
            acc[2][0] += a2 * b0; acc[2][1] += a2 * b1; acc[2][2] += a2 * b2; acc[2][3] += a2 * b3;
            acc[3][0] += a3 * b0; acc[3][1] += a3 * b1; acc[3][2] += a3 * b2; acc[3][3] += a3 * b3;
        }
        __syncthreads();
    }

#pragma unroll
    for (int i = 0; i < 4; i++) {
        int r = block_row + tr + i;
        if (r >= nreal) continue;
#pragma unroll
        for (int j = 0; j < 4; j++) {
            int c = block_col + tc + j;
            if (c >= ncols) continue;
            C[(size_t)r * ld + c] = acc[i][j];
        }
    }
}

// ---------------- score ----------------
__global__ void score_kernel(const float* __restrict__ upd_node, const float* __restrict__ plan,
                             float* __restrict__ out)
{
    int b = blockIdx.x;
    int t = threadIdx.x;
    __shared__ float P[64][64];
    __shared__ float FC[48][128];
    __shared__ float red[128];
    for (int idx = t; idx < 64 * 64; idx += 128)
        P[idx / 64][idx % 64] = plan[(size_t)b * 4096 + idx];
    for (int idx = t; idx < 48 * 128; idx += 128) {
        int c = idx / 128, d = idx % 128;
        FC[c][d] = upd_node[((size_t)(2 * b + 1) * 48 + c) * 768 + 640 + d];
    }
    __syncthreads();
    float acc = 0.f;
    for (int q = 0; q < 64; q++) {
        float s = 0.f;
#pragma unroll 8
        for (int c = 0; c < 48; c++) s += P[q][c] * FC[c][t];
        float fq = 0.f;
        if (q < 48) fq = upd_node[((size_t)(2 * b) * 48 + q) * 768 + 640 + t];
        acc += fmaxf(fq - s, 0.f);
    }
    red[t] = acc;
    __syncthreads();
    for (int s2 = 64; s2 > 0; s2 >>= 1) {
        if (t < s2) red[t] += red[t + s2];
        __syncthreads();
    }
    if (t == 0) out[b] = -red[0];
}

// ---------------- host helpers ----------------
struct Seg { const float* A; int lda; const int* rows; };

static void gemm3(Seg s0, Seg s1, Seg s2, int kb1, int kb2,
                  const float* B, const float* bias,
                  const float* Cin, int ldcin, float cin_scale,
                  float* C, int ldc, int M, int N, int K, int relu)
{
    dim3 g(N / TBN, M / TBM);
    gemm3_kernel<<<g, 256>>>(s0.A, s0.lda, s0.rows, s1.A, s1.lda, s1.rows,
                             s2.A, s2.lda, s2.rows, kb1, kb2,
                             B, bias, Cin, ldcin, cin_scale, C, ldc, M, N, K, relu);
}

static void gemm1(const float* A, int lda, const int* rows,
                  const float* B, const float* bias,
                  const float* Cin, int ldcin, float cin_scale,
                  float* C, int ldc, int M, int N, int K, int relu)
{
    Seg s{A, lda, rows};
    gemm3(s, s, s, K, K, B, bias, Cin, ldcin, cin_scale, C, ldc, M, N, K, relu);
}

static void zero_buf(float* p, size_t n)
{
    int grid = (int)((n + 255) / 256);
    if (grid > 8192) grid = 8192;
    zero_kernel<<<grid, 256>>>(p, n);
}

extern "C" void kernel_launch(void* const* d_in, const int* in_sizes, int n_in,
                              void* d_out, int out_size)
{
    const float* node_features = (const float*)d_in[0];
    const float* edge_features = (const float*)d_in[1];
    const int* from_idx = (const int*)d_in[2];
    const int* to_idx = (const int*)d_in[3];
    const float* enc_node_W = (const float*)d_in[4];
    const float* enc_node_b = (const float*)d_in[5];
    const float* enc_edge_W = (const float*)d_in[6];
    const float* enc_edge_b = (const float*)d_in[7];
    const float* ni_W1 = (const float*)d_in[8];
    const float* ni_b1 = (const float*)d_in[9];
    const float* ni_W2 = (const float*)d_in[10];
    const float* ni_b2 = (const float*)d_in[11];
    const float* ei_W1 = (const float*)d_in[12];
    const float* ei_b1 = (const float*)d_in[13];
    const float* ei_W2 = (const float*)d_in[14];
    const float* ei_b2 = (const float*)d_in[15];
    const float* msg_W = (const float*)d_in[16];
    const float* msg_b = (const float*)d_in[17];
    const float* nu_W1 = (const float*)d_in[18];
    const float* nu_b1 = (const float*)d_in[19];
    const float* nu_W2 = (const float*)d_in[20];
    const float* nu_b2 = (const float*)d_in[21];
    const float* ns_W1 = (const float*)d_in[22];
    const float* ns_b1 = (const float*)d_in[23];
    const float* ns_W2 = (const float*)d_in[24];
    const float* ns_b2 = (const float*)d_in[25];
    const float* es_W1 = (const float*)d_in[26];
    const float* es_b1 = (const float*)d_in[27];
    const float* es_W2 = (const float*)d_in[28];
    const float* es_b2 = (const float*)d_in[29];

    float* S = nullptr;
    cudaGetSymbolAddress((void**)&S, g_scratch);

    float* enc_n = S + OFF_ENC_N;
    float* enc_e = S + OFF_ENC_E;
    float* node_store = S + OFF_NS;
    float* edge_store = S + OFF_ES;
    float* UN = S + OFF_UN;
    float* UE = S + OFF_UE;
    float* tmpN = S + OFF_TMPN;
    float* tmpE = S + OFF_TMPE;
    float* hcomb = S + OFF_HC;
    float* ecomb = S + OFF_EC;
    float* fwd = S + OFF_FWD;
    float* bwd = S + OFF_BWD;
    float* agg = S + OFF_AGG;
    float* TN = S + OFF_TN;
    float* TE = S + OFF_TE;
    float* PLN = S + OFF_PLN;
    float* PLE = S + OFF_PLE;
    float* ewc = S + OFF_EWC;
    float* wab = S + OFF_WAB;

    // one-time zeroing (transport fully overwrites the read regions each K)
    zero_buf(node_store, SZ_NS);
    zero_buf(edge_store, SZ_ES);
    wab_kernel<<<(128 * 256 + 255) / 256, 256>>>(msg_W, wab);

    // encoders
    gemm1(node_features, DIN, nullptr, enc_node_W, enc_node_b, nullptr, 0, 0.f,
          enc_n, 128, VN, 128, DIN, 0);
    gemm1(edge_features, DIN, nullptr, enc_edge_W, enc_edge_b, nullptr, 0, 0.f,
          enc_e, 128, VE, 128, DIN, 0);

    for (int k = 0; k < KK; k++) {
        for (int p = 1; p <= TT; p++) {
            const float* hptr = (p == 1) ? enc_n : (UN + (size_t)(p - 1) * 128);
            int hlda = (p == 1) ? 128 : 768;

            // h_comb = mlp2([h | node_store slice], ni)
            gemm3(Seg{hptr, hlda, nullptr},
                  Seg{node_store + (size_t)(p - 1) * 128, 768, nullptr},
                  Seg{nullptr, 0, nullptr}, 128, 256,
                  ni_W1, ni_b1, nullptr, 0, 0.f, tmpN, 256, VN, 256, 256, 1);
            gemm1(tmpN, 256, nullptr, ni_W2, ni_b2, nullptr, 0, 0.f,
                  hcomb, 128, VN, 128, 256, 0);

            // e_comb = mlp2([enc_e | edge_store slice], ei)
            gemm3(Seg{enc_e, 128, nullptr},
                  Seg{edge_store + (size_t)(p - 1) * 256, 1536, nullptr},
                  Seg{nullptr, 0, nullptr}, 128, 384,
                  ei_W1, ei_b1, nullptr, 0, 0.f, tmpE, 384, VE, 384, 384, 1);
            gemm1(tmpE, 384, nullptr, ei_W2, ei_b2, nullptr, 0, 0.f,
                  ecomb, 128, VE, 128, 384, 0);

            // EWc = ecomb @ msg_W[256:384] + msg_b  (shared by fwd/bwd/msgs2)
            gemm1(ecomb, 128, nullptr, msg_W + 256 * 256, msg_b, nullptr, 0, 0.f,
                  ewc, 256, VE, 256, 128, 0);

            // fwd = [h_comb[from] | h_comb[to]] @ msg_W[0:256] + EWc
            gemm3(Seg{hcomb, 128, from_idx}, Seg{hcomb, 128, to_idx},
                  Seg{nullptr, 0, nullptr}, 128, 256,
                  msg_W, nullptr, ewc, 256, 1.f, fwd, 256, VE, 256, 256, 0);
            // bwd (swapped gathers)
            gemm3(Seg{hcomb, 128, to_idx}, Seg{hcomb, 128, from_idx},
                  Seg{nullptr, 0, nullptr}, 128, 256,
                  msg_W, nullptr, ewc, 256, 1.f, bwd, 256, VE, 256, 256, 0);

            // aggregate
            zero_buf(agg, SZ_AGG);
            {
                size_t tot = (size_t)VE * 256;
                int grid = (int)((tot + 255) / 256);
                scatter_add_kernel<<<grid, 256>>>(fwd, bwd, from_idx, to_idx, agg);
            }

            // h_new = mlp2([h_comb | agg], nu) -> UN slot p
            gemm3(Seg{hcomb, 128, nullptr}, Seg{agg, 256, nullptr},
                  Seg{nullptr, 0, nullptr}, 128, 384,
                  nu_W1, nu_b1, nullptr, 0, 0.f, tmpN, 256, VN, 256, 384, 1);
            gemm1(tmpN, 256, nullptr, nu_W2, nu_b2, nullptr, 0, 0.f,
                  UN + (size_t)p * 128, 768, VN, 128, 256, 0);

            // msgs2 = (h[from]+h[to]) @ (Wa+Wb) + 2*EWc -> UE slot p
            const float* hn = UN + (size_t)p * 128;
            sumsd_kernel<<<(VE * 32 + 255) / 256, 256>>>(hn, from_idx, to_idx, tmpE);
            gemm1(tmpE, 128, nullptr, wab, nullptr, ewc, 256, 2.f,
                  UE + (size_t)p * 256, 1536, VE, 256, 128, 0);
        }

        // ----- node transport -----
        transport_mlp_kernel<<<dim3(MAXN, NGRP), 64>>>(UN, 768, 640, 128, ns_W1, ns_b1,
                                                       ns_W2, ns_b2, TN, MAXN, NPER);
        la_kernel<<<dim3(4, 4, BNUM), dim3(16, 16)>>>(TN, PLN, MAXN);
        for (int it = 0; it < SINK_ITERS; it++) {
            sink_row_kernel<<<BNUM * MAXN, MAXN>>>(PLN, MAXN);
            sink_col_kernel<<<dim3(MAXN / 32, BNUM), dim3(32, 8)>>>(PLN, MAXN);
        }
        exp_kernel<<<1024, 256>>>(PLN, SZ_PLN);
        trans_apply_kernel<<<dim3(10, 1, NGRP), 256>>>(PLN, UN, node_store, MAXN, NPER, 768, 128);

        // ----- edge transport -----
        transport_mlp_kernel<<<dim3(MAXE, NGRP), 64>>>(UE, 1536, 1280, 256, es_W1, es_b1,
                                                       es_W2, es_b2, TE, MAXE, EPER);
        la_kernel<<<dim3(16, 16, BNUM), dim3(16, 16)>>>(TE, PLE, MAXE);
        for (int it = 0; it < SINK_ITERS; it++) {
            sink_row_kernel<<<BNUM * MAXE, MAXE>>>(PLE, MAXE);
            sink_col_kernel<<<dim3(MAXE / 32, BNUM), dim3(32, 8)>>>(PLE, MAXE);
        }
        exp_kernel<<<8192, 256>>>(PLE, SZ_PLE);
        trans_apply_kernel<<<dim3(20, 3, NGRP), 256>>>(PLE, UE, edge_store, MAXE, EPER, 1536, 256);
    }

    // ----- score -----
    score_kernel<<<BNUM, 128>>>(UN, PLN, (float*)d_out);
}

// round 4
// speedup vs baseline: 2.2308x; 1.2510x over previous
#include <cuda_runtime.h>
#include <cuda_bf16.h>
#include <math.h>

// ---------------- constants ----------------
#define BNUM 64
#define NGRP 128
#define NPER 48
#define EPER 192
#define MAXN 64
#define MAXE 256
#define DIN 32
#define TT 5
#define KK 3
#define VN 6144
#define VE 24576
#define INV_TEMP 10.0f
#define SINK_ITERS 10

// ---------------- scratch layout (floats) ----------------
#define SZ_ENC_N ((size_t)VN * 128)
#define SZ_ENC_E ((size_t)VE * 128)
#define SZ_NS ((size_t)VN * 768)
#define SZ_ES ((size_t)VE * 1536)
#define SZ_UN ((size_t)VN * 768)
#define SZ_UE ((size_t)VE * 1536)
#define SZ_TMPN ((size_t)VN * 256)
#define SZ_TMPE ((size_t)VE * 384)
#define SZ_HC ((size_t)VN * 128)
#define SZ_EC ((size_t)VE * 128)
#define SZ_FWD ((size_t)VE * 256)
#define SZ_AGG ((size_t)VN * 256)
#define SZ_TN ((size_t)NGRP * 64 * 64)
#define SZ_TE ((size_t)NGRP * 256 * 64)
#define SZ_PLN ((size_t)BNUM * 64 * 64)
#define SZ_PLE ((size_t)BNUM * 256 * 256)
#define SZ_EWC ((size_t)VE * 256)
#define SZ_WAB ((size_t)128 * 256)

#define OFF_ENC_N ((size_t)0)
#define OFF_ENC_E (OFF_ENC_N + SZ_ENC_N)
#define OFF_NS (OFF_ENC_E + SZ_ENC_E)
#define OFF_ES (OFF_NS + SZ_NS)
#define OFF_UN (OFF_ES + SZ_ES)
#define OFF_UE (OFF_UN + SZ_UN)
#define OFF_TMPN (OFF_UE + SZ_UE)
#define OFF_TMPE (OFF_TMPN + SZ_TMPN)
#define OFF_HC (OFF_TMPE + SZ_TMPE)
#define OFF_EC (OFF_HC + SZ_HC)
#define OFF_FWD (OFF_EC + SZ_EC)
#define OFF_BWD (OFF_FWD + SZ_FWD)
#define OFF_AGG (OFF_BWD + SZ_FWD)
#define OFF_TN (OFF_AGG + SZ_AGG)
#define OFF_TE (OFF_TN + SZ_TN)
#define OFF_PLN (OFF_TE + SZ_TE)
#define OFF_PLE (OFF_PLN + SZ_PLN)
#define OFF_EWC (OFF_PLE + SZ_PLE)
#define OFF_WAB (OFF_EWC + SZ_EWC)
#define SCRATCH_TOTAL (OFF_WAB + SZ_WAB)

__device__ float g_scratch[SCRATCH_TOTAL];

// =====================================================================
// Templated SGEMM: C[M,N] = concat_K(A0|A1|A2) @ B + bias + s*Cin (relu)
// Split-tile 8x8 microtile: rows {r0..r0+3, r0+BM/2..}, cols {c0..c0+3,
// c0+BN/2..} -> conflict-free LDS.128 fragments & float4 epilogue.
// Dual mode (gridDim.z==2): block z==1 swaps seg0/seg1 gather arrays and
// writes C_dual (fwd/bwd message pair in one launch).
// Requirements: M%BM==0, N%BN==0, K%16==0, kb1/kb2 multiples of 16,
// ldb==N, all pointers 16B aligned, lda%4==0.
// =====================================================================
template <int BM, int BN, int NT>
__global__ __launch_bounds__(NT, 2) void gemm3_t(
    const float* __restrict__ A0, int lda0, const int* __restrict__ r0a,
    const float* __restrict__ A1, int lda1, const int* __restrict__ r1a,
    const float* __restrict__ A2, int lda2, const int* __restrict__ r2a,
    int kb1, int kb2,
    const float* __restrict__ B,
    const float* __restrict__ bias,
    const float* __restrict__ Cin, int ldcin, float cin_scale,
    float* __restrict__ C, float* __restrict__ C_dual, int ldc,
    int Ndim, int Kdim, int relu)
{
    constexpr int BK = 16;
    __shared__ __align__(16) float As[BK][BM];
    __shared__ __align__(16) float Bs[BK][BN];

    const int tid = threadIdx.x;
    const int row0 = blockIdx.y * BM;
    const int col0 = blockIdx.x * BN;

    const int* g0 = r0a;
    const int* g1 = r1a;
    float* Cout = C;
    if (blockIdx.z == 1) { g0 = r1a; g1 = r0a; Cout = C_dual; }

    const int c0 = (tid & 15) << 2;        // 0..60
    const int r0 = (tid >> 4) << 2;        // 0..(BM/2-4)

    float acc[8][8];
#pragma unroll
    for (int i = 0; i < 8; i++)
#pragma unroll
        for (int j = 0; j < 8; j++) acc[i][j] = 0.f;

    for (int k0 = 0; k0 < Kdim; k0 += BK) {
        const float* Ap; int lda; const int* rows; int kloc;
        if (k0 < kb1) { Ap = A0; lda = lda0; rows = g0; kloc = k0; }
        else if (k0 < kb2) { Ap = A1; lda = lda1; rows = g1; kloc = k0 - kb1; }
        else { Ap = A2; lda = lda2; rows = r2a; kloc = k0 - kb2; }

        // A tile: BM rows x 16 k  -> BM*4 float4 loads
#pragma unroll
        for (int u = 0; u < (BM * 4) / NT; u++) {
            int idx = tid + u * NT;
            int m = idx & (BM - 1);
            int kj = (idx / BM) * 4;
            int gm = row0 + m;
            int arow = rows ? __ldg(&rows[gm]) : gm;
            float4 v = *(const float4*)(Ap + (size_t)arow * lda + kloc + kj);
            As[kj + 0][m] = v.x;
            As[kj + 1][m] = v.y;
            As[kj + 2][m] = v.z;
            As[kj + 3][m] = v.w;
        }
        // B tile: 16 x BN -> 4*BN float4 loads
#pragma unroll
        for (int u = 0; u < (4 * BN) / NT; u++) {
            int idx = tid + u * NT;
            int kk = idx / (BN / 4);
            int n4 = (idx & (BN / 4 - 1)) * 4;
            *(float4*)&Bs[kk][n4] = *(const float4*)(B + (size_t)(k0 + kk) * Ndim + col0 + n4);
        }
        __syncthreads();

#pragma unroll
        for (int kk = 0; kk < BK; kk++) {
            float a[8], b[8];
            *(float4*)(a) = *(const float4*)&As[kk][r0];
            *(float4*)(a + 4) = *(const float4*)&As[kk][r0 + BM / 2];
            *(float4*)(b) = *(const float4*)&Bs[kk][c0];
            *(float4*)(b + 4) = *(const float4*)&Bs[kk][c0 + BN / 2];
#pragma unroll
            for (int i = 0; i < 8; i++)
#pragma unroll
                for (int j = 0; j < 8; j++)
                    acc[i][j] += a[i] * b[j];
        }
        __syncthreads();
    }

    // epilogue (float4)
    float4 blo = make_float4(0.f, 0.f, 0.f, 0.f), bhi = blo;
    if (bias) {
        blo = *(const float4*)(bias + col0 + c0);
        bhi = *(const float4*)(bias + col0 + BN / 2 + c0);
    }
#pragma unroll
    for (int i = 0; i < 8; i++) {
        int r = row0 + ((i < 4) ? (r0 + i) : (BM / 2 + r0 + i - 4));
        float4 lo = make_float4(acc[i][0], acc[i][1], acc[i][2], acc[i][3]);
        float4 hi = make_float4(acc[i][4], acc[i][5], acc[i][6], acc[i][7]);
        lo.x += blo.x; lo.y += blo.y; lo.z += blo.z; lo.w += blo.w;
        hi.x += bhi.x; hi.y += bhi.y; hi.z += bhi.z; hi.w += bhi.w;
        if (Cin) {
            const float* cr = Cin + (size_t)r * ldcin + col0;
            float4 clo = *(const float4*)(cr + c0);
            float4 chi = *(const float4*)(cr + BN / 2 + c0);
            lo.x += cin_scale * clo.x; lo.y += cin_scale * clo.y;
            lo.z += cin_scale * clo.z; lo.w += cin_scale * clo.w;
            hi.x += cin_scale * chi.x; hi.y += cin_scale * chi.y;
            hi.z += cin_scale * chi.z; hi.w += cin_scale * chi.w;
        }
        if (relu) {
            lo.x = fmaxf(lo.x, 0.f); lo.y = fmaxf(lo.y, 0.f);
            lo.z = fmaxf(lo.z, 0.f); lo.w = fmaxf(lo.w, 0.f);
            hi.x = fmaxf(hi.x, 0.f); hi.y = fmaxf(hi.y, 0.f);
            hi.z = fmaxf(hi.z, 0.f); hi.w = fmaxf(hi.w, 0.f);
        }
        float* crow = Cout + (size_t)r * ldc + col0;
        *(float4*)(crow + c0) = lo;
        *(float4*)(crow + BN / 2 + c0) = hi;
    }
}

// ---------------- misc elementwise ----------------
__global__ void zero_kernel(float* __restrict__ p, size_t n) {
    size_t i = (size_t)blockIdx.x * blockDim.x + threadIdx.x;
    size_t stride = (size_t)gridDim.x * blockDim.x;
    for (; i < n; i += stride) p[i] = 0.f;
}

__global__ void wab_kernel(const float* __restrict__ msgW, float* __restrict__ wab) {
    int i = blockIdx.x * blockDim.x + threadIdx.x;
    if (i < 128 * 256) wab[i] = msgW[i] + msgW[128 * 256 + i];
}

// sumsd[e][0:128] = hn[from[e]] + hn[to[e]]  (hn stride 768), float4
__global__ void sumsd_kernel(const float* __restrict__ hn, const int* __restrict__ from_idx,
                             const int* __restrict__ to_idx, float* __restrict__ out)
{
    int i = blockIdx.x * blockDim.x + threadIdx.x;
    if (i >= VE * 32) return;
    int e = i >> 5;
    int c4 = (i & 31) << 2;
    const float4 a = *(const float4*)(hn + (size_t)from_idx[e] * 768 + c4);
    const float4 b = *(const float4*)(hn + (size_t)to_idx[e] * 768 + c4);
    float4 o;
    o.x = a.x + b.x; o.y = a.y + b.y; o.z = a.z + b.z; o.w = a.w + b.w;
    *(float4*)(out + (size_t)e * 128 + c4) = o;
}

// ---------------- message aggregation scatter ----------------
__global__ void scatter_add_kernel(const float* __restrict__ fwd, const float* __restrict__ bwd,
                                   const int* __restrict__ from_idx, const int* __restrict__ to_idx,
                                   float* __restrict__ agg)
{
    size_t i = (size_t)blockIdx.x * blockDim.x + threadIdx.x;
    if (i >= (size_t)VE * 256) return;
    int e = (int)(i >> 8);
    int c = (int)(i & 255);
    atomicAdd(&agg[(size_t)to_idx[e] * 256 + c], fwd[i]);
    atomicAdd(&agg[(size_t)from_idx[e] * 256 + c], bwd[i]);
}

// ---------------- transport MLP (fdim -> 64 -> 64, pad rows zero) ----------------
__global__ void transport_mlp_kernel(const float* __restrict__ upd, int ld, int foff, int fdim,
                                     const float* __restrict__ W1, const float* __restrict__ b1,
                                     const float* __restrict__ W2, const float* __restrict__ b2,
                                     float* __restrict__ tout, int maxr, int nreal)
{
    int i = blockIdx.x;
    int g = blockIdx.y;
    int j = threadIdx.x;
    size_t outoff = ((size_t)g * maxr + i) * 64 + j;
    if (i >= nreal) { tout[outoff] = 0.f; return; }
    __shared__ float f[256];
    __shared__ float hid[64];
    const float* frow = upd + ((size_t)g * nreal + i) * ld + foff;
    for (int k = j; k < fdim; k += 64) f[k] = frow[k];
    __syncthreads();
    float h = b1[j];
    for (int k = 0; k < fdim; k++) h += f[k] * W1[k * 64 + j];
    hid[j] = fmaxf(h, 0.f);
    __syncthreads();
    float o = b2[j];
#pragma unroll
    for (int k = 0; k < 64; k++) o += hid[k] * W2[k * 64 + j];
    tout[outoff] = o;
}

// ---------------- la = (tq @ tc^T) / TEMP ----------------
__global__ void la_kernel(const float* __restrict__ t, float* __restrict__ la, int maxr)
{
    __shared__ float Tq[16][65];
    __shared__ float Tc[16][65];
    int b = blockIdx.z;
    int q0 = blockIdx.y * 16;
    int c0 = blockIdx.x * 16;
    const float* tq = t + (size_t)(2 * b) * maxr * 64;
    const float* tc = t + (size_t)(2 * b + 1) * maxr * 64;
    int ty = threadIdx.y, tx = threadIdx.x;
    int lin = ty * 16 + tx;
#pragma unroll
    for (int u = 0; u < 4; u++) {
        int idx = lin + u * 256;
        int r = idx / 64, k = idx % 64;
        Tq[r][k] = tq[(size_t)(q0 + r) * 64 + k];
        Tc[r][k] = tc[(size_t)(c0 + r) * 64 + k];
    }
    __syncthreads();
    float s = 0.f;
#pragma unroll
    for (int k = 0; k < 64; k++) s += Tq[ty][k] * Tc[tx][k];
    la[((size_t)b * maxr + q0 + ty) * maxr + c0 + tx] = s * INV_TEMP;
}

// ---------------- fused node Sinkhorn: smem-resident 64x64, 10 iters + exp
__global__ __launch_bounds__(256) void node_sink_kernel(float* __restrict__ la)
{
    __shared__ float L[64][65];
    float* base = la + (size_t)blockIdx.x * 4096;
    int tid = threadIdx.x;
    for (int i = tid; i < 4096; i += 256) L[i >> 6][i & 63] = base[i];
    __syncthreads();
    int r = tid >> 2;
    int part = (tid & 3) * 16;
    for (int iter = 0; iter < SINK_ITERS; iter++) {
        // row pass (normalize over columns)
        {
            float m = -INFINITY;
#pragma unroll
            for (int i = 0; i < 16; i++) m = fmaxf(m, L[r][part + i]);
            m = fmaxf(m, __shfl_xor_sync(0xFFFFFFFFu, m, 1));
            m = fmaxf(m, __shfl_xor_sync(0xFFFFFFFFu, m, 2));
            float s = 0.f;
#pragma unroll
            for (int i = 0; i < 16; i++) s += expf(L[r][part + i] - m);
            s += __shfl_xor_sync(0xFFFFFFFFu, s, 1);
            s += __shfl_xor_sync(0xFFFFFFFFu, s, 2);
            float lse = m + logf(s);
#pragma unroll
            for (int i = 0; i < 16; i++) L[r][part + i] -= lse;
        }
        __syncthreads();
        // col pass (normalize over rows); r acts as column index
        {
            float m = -INFINITY;
#pragma unroll
            for (int i = 0; i < 16; i++) m = fmaxf(m, L[part + i][r]);
            m = fmaxf(m, __shfl_xor_sync(0xFFFFFFFFu, m, 1));
            m = fmaxf(m, __shfl_xor_sync(0xFFFFFFFFu, m, 2));
            float s = 0.f;
#pragma unroll
            for (int i = 0; i < 16; i++) s += expf(L[part + i][r] - m);
            s += __shfl_xor_sync(0xFFFFFFFFu, s, 1);
            s += __shfl_xor_sync(0xFFFFFFFFu, s, 2);
            float lse = m + logf(s);
#pragma unroll
            for (int i = 0; i < 16; i++) L[part + i][r] -= lse;
        }
        __syncthreads();
    }
    for (int i = tid; i < 4096; i += 256) base[i] = expf(L[i >> 6][i & 63]);
}

// ---------------- fused edge Sinkhorn: L2-resident 256x256, 10 iters + exp
__global__ __launch_bounds__(1024) void edge_sink_kernel(float* __restrict__ la)
{
    float* base = la + (size_t)blockIdx.x * 65536;
    int tid = threadIdx.x;
    int wid = tid >> 5, lane = tid & 31;
    __shared__ float cr[4][256];
    int c = tid & 255, g = tid >> 8;
    for (int iter = 0; iter < SINK_ITERS; iter++) {
        // row pass: warp per row
        for (int r = wid; r < 256; r += 32) {
            float* rp = base + (size_t)r * 256;
            float4 v0 = *(float4*)(rp + lane * 4);
            float4 v1 = *(float4*)(rp + 128 + lane * 4);
            float m = fmaxf(fmaxf(fmaxf(v0.x, v0.y), fmaxf(v0.z, v0.w)),
                            fmaxf(fmaxf(v1.x, v1.y), fmaxf(v1.z, v1.w)));
#pragma unroll
            for (int o = 16; o > 0; o >>= 1) m = fmaxf(m, __shfl_xor_sync(0xFFFFFFFFu, m, o));
            float s = expf(v0.x - m) + expf(v0.y - m) + expf(v0.z - m) + expf(v0.w - m)
                    + expf(v1.x - m) + expf(v1.y - m) + expf(v1.z - m) + expf(v1.w - m);
#pragma unroll
            for (int o = 16; o > 0; o >>= 1) s += __shfl_xor_sync(0xFFFFFFFFu, s, o);
            float lse = m + logf(s);
            v0.x -= lse; v0.y -= lse; v0.z -= lse; v0.w -= lse;
            v1.x -= lse; v1.y -= lse; v1.z -= lse; v1.w -= lse;
            *(float4*)(rp + lane * 4) = v0;
            *(float4*)(rp + 128 + lane * 4) = v1;
        }
        __syncthreads();
        // col pass: thread per (column, quarter)
        float m = -INFINITY;
        for (int r = g * 64; r < g * 64 + 64; r++) m = fmaxf(m, base[(size_t)r * 256 + c]);
        cr[g][c] = m;
        __syncthreads();
        if (g == 0) cr[0][c] = fmaxf(fmaxf(cr[0][c], cr[1][c]), fmaxf(cr[2][c], cr[3][c]));
        __syncthreads();
        m = cr[0][c];
        float s = 0.f;
        for (int r = g * 64; r < g * 64 + 64; r++) s += expf(base[(size_t)r * 256 + c] - m);
        __syncthreads();
        cr[g][c] = s;
        __syncthreads();
        if (g == 0) cr[0][c] = m + logf(cr[0][c] + cr[1][c] + cr[2][c] + cr[3][c]);
        __syncthreads();
        float lse = cr[0][c];
        bool last = (iter == SINK_ITERS - 1);
        for (int r = g * 64; r < g * 64 + 64; r++) {
            float v = base[(size_t)r * 256 + c] - lse;
            base[(size_t)r * 256 + c] = last ? expf(v) : v;
        }
        __syncthreads();
    }
}

// ---------------- plan apply ----------------
#define GBM 64
#define GBN 64
#define GBK 16
__global__ __launch_bounds__(256) void trans_apply_kernel(
    const float* __restrict__ plan, const float* __restrict__ upd,
    float* __restrict__ store, int maxr, int nreal, int ld, int coff)
{
    __shared__ float Ps[GBK][GBM];
    __shared__ float Fs[GBK][GBN];
    int z = blockIdx.z;
    int b = z >> 1;
    int mode = z & 1;
    const float* P = plan + (size_t)b * maxr * maxr;
    int fgrp = 2 * b + (mode ? 0 : 1);
    int ogrp = 2 * b + mode;
    const float* F = upd + (size_t)fgrp * nreal * ld + coff;
    float* C = store + (size_t)ogrp * nreal * ld + coff;
    int ncols = ld - coff;
    int block_row = blockIdx.y * GBM;
    int block_col = blockIdx.x * GBN;
    int tid = threadIdx.x;
    float acc[4][4];
#pragma unroll
    for (int i = 0; i < 4; i++)
#pragma unroll
        for (int j = 0; j < 4; j++) acc[i][j] = 0.f;
    int tr = (tid / 16) * 4;
    int tc = (tid % 16) * 4;

    for (int k0 = 0; k0 < nreal; k0 += GBK) {
#pragma unroll
        for (int u = 0; u < 4; u++) {
            int idx = tid + u * 256;
            int m = idx / GBK;
            int k = idx % GBK;
            int gr = block_row + m;
            int gk = k0 + k;
            float v = 0.f;
            if (gr < nreal && gk < nreal)
                v = mode ? P[(size_t)gk * maxr + gr] : P[(size_t)gr * maxr + gk];
            Ps[k][m] = v;
        }
#pragma unroll
        for (int u = 0; u < 4; u++) {
            int idx = tid + u * 256;
            int k = idx / GBN;
            int n = idx % GBN;
            int gk = k0 + k;
            int gn = block_col + n;
            float v = 0.f;
            if (gk < nreal && gn < ncols) v = F[(size_t)gk * ld + gn];
            Fs[k][n] = v;
        }
        __syncthreads();
#pragma unroll
        for (int k = 0; k < GBK; k++) {
            float a0 = Ps[k][tr], a1 = Ps[k][tr + 1], a2 = Ps[k][tr + 2], a3 = Ps[k][tr + 3];
            float b0 = Fs[k][tc], b1 = Fs[k][tc + 1], b2 = Fs[k][tc + 2], b3 = Fs[k][tc + 3];
            acc[0][0] += a0 * b0; acc[0][1] += a0 * b1; acc[0][2] += a0 * b2; acc[0][3] += a0 * b3;
            acc[1][0] += a1 * b0; acc[1][1] += a1 * b1; acc[1][2] += a1 * b2; acc[1][3] += a1 * b3;
            acc[2][0] += a2 * b0; acc[2][1] += a2 * b1; acc[2][2] += a2 * b2; acc[2][3] += a2 * b3;
            acc[3][0] += a3 * b0; acc[3][1] += a3 * b1; acc[3][2] += a3 * b2; acc[3][3] += a3 * b3;
        }
        __syncthreads();
    }

#pragma unroll
    for (int i = 0; i < 4; i++) {
        int r = block_row + tr + i;
        if (r >= nreal) continue;
#pragma unroll
        for (int j = 0; j < 4; j++) {
            int c = block_col + tc + j;
            if (c >= ncols) continue;
            C[(size_t)r * ld + c] = acc[i][j];
        }
    }
}

// ---------------- score ----------------
__global__ void score_kernel(const float* __restrict__ upd_node, const float* __restrict__ plan,
                             float* __restrict__ out)
{
    int b = blockIdx.x;
    int t = threadIdx.x;
    __shared__ float P[64][64];
    __shared__ float FC[48][128];
    __shared__ float red[128];
    for (int idx = t; idx < 64 * 64; idx += 128)
        P[idx / 64][idx % 64] = plan[(size_t)b * 4096 + idx];
    for (int idx = t; idx < 48 * 128; idx += 128) {
        int c = idx / 128, d = idx % 128;
        FC[c][d] = upd_node[((size_t)(2 * b + 1) * 48 + c) * 768 + 640 + d];
    }
    __syncthreads();
    float acc = 0.f;
    for (int q = 0; q < 64; q++) {
        float s = 0.f;
#pragma unroll 8
        for (int c = 0; c < 48; c++) s += P[q][c] * FC[c][t];
        float fq = 0.f;
        if (q < 48) fq = upd_node[((size_t)(2 * b) * 48 + q) * 768 + 640 + t];
        acc += fmaxf(fq - s, 0.f);
    }
    red[t] = acc;
    __syncthreads();
    for (int s2 = 64; s2 > 0; s2 >>= 1) {
        if (t < s2) red[t] += red[t + s2];
        __syncthreads();
    }
    if (t == 0) out[b] = -red[0];
}

// ---------------- host helpers ----------------
struct Seg { const float* A; int lda; const int* rows; };

// big: 128x128 tile, 256 thr (use for M=VE). small: 64x128, 128 thr (M=VN).
static void gemmB(Seg s0, Seg s1, Seg s2, int kb1, int kb2,
                  const float* B, const float* bias,
                  const float* Cin, int ldcin, float cs,
                  float* C, float* Cd, int ldc, int M, int N, int K, int relu, int dual)
{
    dim3 g(N / 128, M / 128, dual ? 2 : 1);
    gemm3_t<128, 128, 256><<<g, 256>>>(s0.A, s0.lda, s0.rows, s1.A, s1.lda, s1.rows,
                                       s2.A, s2.lda, s2.rows, kb1, kb2,
                                       B, bias, Cin, ldcin, cs, C, Cd, ldc, N, K, relu);
}

static void gemmS(Seg s0, Seg s1, Seg s2, int kb1, int kb2,
                  const float* B, const float* bias,
                  const float* Cin, int ldcin, float cs,
                  float* C, int ldc, int M, int N, int K, int relu)
{
    dim3 g(N / 128, M / 64, 1);
    gemm3_t<64, 128, 128><<<g, 128>>>(s0.A, s0.lda, s0.rows, s1.A, s1.lda, s1.rows,
                                      s2.A, s2.lda, s2.rows, kb1, kb2,
                                      B, bias, Cin, ldcin, cs, C, nullptr, ldc, N, K, relu);
}

static void zero_buf(float* p, size_t n)
{
    int grid = (int)((n + 255) / 256);
    if (grid > 8192) grid = 8192;
    zero_kernel<<<grid, 256>>>(p, n);
}

extern "C" void kernel_launch(void* const* d_in, const int* in_sizes, int n_in,
                              void* d_out, int out_size)
{
    const float* node_features = (const float*)d_in[0];
    const float* edge_features = (const float*)d_in[1];
    const int* from_idx = (const int*)d_in[2];
    const int* to_idx = (const int*)d_in[3];
    const float* enc_node_W = (const float*)d_in[4];
    const float* enc_node_b = (const float*)d_in[5];
    const float* enc_edge_W = (const float*)d_in[6];
    const float* enc_edge_b = (const float*)d_in[7];
    const float* ni_W1 = (const float*)d_in[8];
    const float* ni_b1 = (const float*)d_in[9];
    const float* ni_W2 = (const float*)d_in[10];
    const float* ni_b2 = (const float*)d_in[11];
    const float* ei_W1 = (const float*)d_in[12];
    const float* ei_b1 = (const float*)d_in[13];
    const float* ei_W2 = (const float*)d_in[14];
    const float* ei_b2 = (const float*)d_in[15];
    const float* msg_W = (const float*)d_in[16];
    const float* msg_b = (const float*)d_in[17];
    const float* nu_W1 = (const float*)d_in[18];
    const float* nu_b1 = (const float*)d_in[19];
    const float* nu_W2 = (const float*)d_in[20];
    const float* nu_b2 = (const float*)d_in[21];
    const float* ns_W1 = (const float*)d_in[22];
    const float* ns_b1 = (const float*)d_in[23];
    const float* ns_W2 = (const float*)d_in[24];
    const float* ns_b2 = (const float*)d_in[25];
    const float* es_W1 = (const float*)d_in[26];
    const float* es_b1 = (const float*)d_in[27];
    const float* es_W2 = (const float*)d_in[28];
    const float* es_b2 = (const float*)d_in[29];

    float* S = nullptr;
    cudaGetSymbolAddress((void**)&S, g_scratch);

    float* enc_n = S + OFF_ENC_N;
    float* enc_e = S + OFF_ENC_E;
    float* node_store = S + OFF_NS;
    float* edge_store = S + OFF_ES;
    float* UN = S + OFF_UN;
    float* UE = S + OFF_UE;
    float* tmpN = S + OFF_TMPN;
    float* tmpE = S + OFF_TMPE;
    float* hcomb = S + OFF_HC;
    float* ecomb = S + OFF_EC;
    float* fwd = S + OFF_FWD;
    float* bwd = S + OFF_BWD;
    float* agg = S + OFF_AGG;
    float* TN = S + OFF_TN;
    float* TE = S + OFF_TE;
    float* PLN = S + OFF_PLN;
    float* PLE = S + OFF_PLE;
    float* ewc = S + OFF_EWC;
    float* wab = S + OFF_WAB;

    Seg none{nullptr, 0, nullptr};

    // one-time zeroing (transport fully overwrites the read regions each K)
    zero_buf(node_store, SZ_NS);
    zero_buf(edge_store, SZ_ES);
    wab_kernel<<<(128 * 256 + 255) / 256, 256>>>(msg_W, wab);

    // encoders
    gemmS(Seg{node_features, DIN, nullptr}, none, none, 32, 32,
          enc_node_W, enc_node_b, nullptr, 0, 0.f, enc_n, 128, VN, 128, 32, 0);
    gemmB(Seg{edge_features, DIN, nullptr}, none, none, 32, 32,
          enc_edge_W, enc_edge_b, nullptr, 0, 0.f, enc_e, nullptr, 128, VE, 128, 32, 0, 0);

    for (int k = 0; k < KK; k++) {
        for (int p = 1; p <= TT; p++) {
            const float* hptr = (p == 1) ? enc_n : (UN + (size_t)(p - 1) * 128);
            int hlda = (p == 1) ? 128 : 768;

            // h_comb = mlp2([h | node_store slice], ni)
            gemmS(Seg{hptr, hlda, nullptr},
                  Seg{node_store + (size_t)(p - 1) * 128, 768, nullptr}, none, 128, 256,
                  ni_W1, ni_b1, nullptr, 0, 0.f, tmpN, 256, VN, 256, 256, 1);
            gemmS(Seg{tmpN, 256, nullptr}, none, none, 256, 256,
                  ni_W2, ni_b2, nullptr, 0, 0.f, hcomb, 128, VN, 128, 256, 0);

            // e_comb = mlp2([enc_e | edge_store slice], ei)
            gemmB(Seg{enc_e, 128, nullptr},
                  Seg{edge_store + (size_t)(p - 1) * 256, 1536, nullptr}, none, 128, 384,
                  ei_W1, ei_b1, nullptr, 0, 0.f, tmpE, nullptr, 384, VE, 384, 384, 1, 0);
            gemmB(Seg{tmpE, 384, nullptr}, none, none, 384, 384,
                  ei_W2, ei_b2, nullptr, 0, 0.f, ecomb, nullptr, 128, VE, 128, 384, 0, 0);

            // EWc = ecomb @ msg_W[256:384] + msg_b
            gemmB(Seg{ecomb, 128, nullptr}, none, none, 128, 128,
                  msg_W + 256 * 256, msg_b, nullptr, 0, 0.f, ewc, nullptr, 256, VE, 256, 128, 0, 0);

            // fwd & bwd in ONE dual launch:
            //   fwd = [h_comb[from] | h_comb[to]] @ msg_W[0:256] + EWc
            //   bwd = swapped gathers
            gemmB(Seg{hcomb, 128, from_idx}, Seg{hcomb, 128, to_idx}, none, 128, 256,
                  msg_W, nullptr, ewc, 256, 1.f, fwd, bwd, 256, VE, 256, 256, 0, 1);

            // aggregate
            zero_buf(agg, SZ_AGG);
            {
                size_t tot = (size_t)VE * 256;
                int grid = (int)((tot + 255) / 256);
                scatter_add_kernel<<<grid, 256>>>(fwd, bwd, from_idx, to_idx, agg);
            }

            // h_new = mlp2([h_comb | agg], nu) -> UN slot p
            gemmS(Seg{hcomb, 128, nullptr}, Seg{agg, 256, nullptr}, none, 128, 384,
                  nu_W1, nu_b1, nullptr, 0, 0.f, tmpN, 256, VN, 256, 384, 1);
            gemmS(Seg{tmpN, 256, nullptr}, none, none, 256, 256,
                  nu_W2, nu_b2, nullptr, 0, 0.f, UN + (size_t)p * 128, 768, VN, 128, 256, 0);

            // msgs2 = (h[from]+h[to]) @ (Wa+Wb) + 2*EWc -> UE slot p
            const float* hn = UN + (size_t)p * 128;
            sumsd_kernel<<<(VE * 32 + 255) / 256, 256>>>(hn, from_idx, to_idx, tmpE);
            gemmB(Seg{tmpE, 128, nullptr}, none, none, 128, 128,
                  wab, nullptr, ewc, 256, 2.f, UE + (size_t)p * 256, nullptr, 1536, VE, 256, 128, 0, 0);
        }

        // ----- node transport -----
        transport_mlp_kernel<<<dim3(MAXN, NGRP), 64>>>(UN, 768, 640, 128, ns_W1, ns_b1,
                                                       ns_W2, ns_b2, TN, MAXN, NPER);
        la_kernel<<<dim3(4, 4, BNUM), dim3(16, 16)>>>(TN, PLN, MAXN);
        node_sink_kernel<<<BNUM, 256>>>(PLN);
        trans_apply_kernel<<<dim3(10, 1, NGRP), 256>>>(PLN, UN, node_store, MAXN, NPER, 768, 128);

        // ----- edge transport -----
        transport_mlp_kernel<<<dim3(MAXE, NGRP), 64>>>(UE, 1536, 1280, 256, es_W1, es_b1,
                                                       es_W2, es_b2, TE, MAXE, EPER);
        la_kernel<<<dim3(16, 16, BNUM), dim3(16, 16)>>>(TE, PLE, MAXE);
        edge_sink_kernel<<<BNUM, 1024>>>(PLE);
        trans_apply_kernel<<<dim3(20, 3, NGRP), 256>>>(PLE, UE, edge_store, MAXE, EPER, 1536, 256);
    }

    // ----- score -----
    score_kernel<<<BNUM, 128>>>(UN, PLN, (float*)d_out);
}

// round 5
// speedup vs baseline: 3.0384x; 1.3620x over previous
#include <cuda_runtime.h>
#include <cuda_bf16.h>
#include <math.h>
#include <stdint.h>

// ---------------- constants ----------------
#define BNUM 64
#define NGRP 128
#define NPER 48
#define EPER 192
#define MAXN 64
#define MAXE 256
#define DIN 32
#define TT 5
#define KK 3
#define VN 6144
#define VE 24576
#define INV_TEMP 10.0f
#define SINK_ITERS 10

// ---------------- scratch layout (floats) ----------------
#define SZ_ENC_N ((size_t)VN * 128)
#define SZ_ENC_E ((size_t)VE * 128)
#define SZ_NS ((size_t)VN * 768)
#define SZ_ES ((size_t)VE * 1536)
#define SZ_UN ((size_t)VN * 768)
#define SZ_UE ((size_t)VE * 1536)
#define SZ_TMPN ((size_t)VN * 256)
#define SZ_TMPE ((size_t)VE * 384)
#define SZ_HC ((size_t)VN * 128)
#define SZ_EC ((size_t)VE * 128)
#define SZ_FWD ((size_t)VE * 256)
#define SZ_AGG ((size_t)VN * 256)
#define SZ_TN ((size_t)NGRP * 64 * 64)
#define SZ_TE ((size_t)NGRP * 256 * 64)
#define SZ_PLN ((size_t)BNUM * 64 * 64)
#define SZ_PLE ((size_t)BNUM * 256 * 256)
#define SZ_EWC ((size_t)VE * 256)
#define SZ_WAB ((size_t)128 * 256)

#define OFF_ENC_N ((size_t)0)
#define OFF_ENC_E (OFF_ENC_N + SZ_ENC_N)
#define OFF_NS (OFF_ENC_E + SZ_ENC_E)
#define OFF_ES (OFF_NS + SZ_NS)
#define OFF_UN (OFF_ES + SZ_ES)
#define OFF_UE (OFF_UN + SZ_UN)
#define OFF_TMPN (OFF_UE + SZ_UE)
#define OFF_TMPE (OFF_TMPN + SZ_TMPN)
#define OFF_HC (OFF_TMPE + SZ_TMPE)
#define OFF_EC (OFF_HC + SZ_HC)
#define OFF_FWD (OFF_EC + SZ_EC)
#define OFF_BWD (OFF_FWD + SZ_FWD)
#define OFF_AGG (OFF_BWD + SZ_FWD)
#define OFF_TN (OFF_AGG + SZ_AGG)
#define OFF_TE (OFF_TN + SZ_TN)
#define OFF_PLN (OFF_TE + SZ_TE)
#define OFF_PLE (OFF_PLN + SZ_PLN)
#define OFF_EWC (OFF_PLE + SZ_PLE)
#define OFF_WAB (OFF_EWC + SZ_EWC)
#define SCRATCH_TOTAL (OFF_WAB + SZ_WAB)

__device__ float g_scratch[SCRATCH_TOTAL];

// ---------------- mma helpers ----------------
__device__ __forceinline__ uint32_t s2u(const void* p) {
    return (uint32_t)__cvta_generic_to_shared(p);
}

#define LDSM4(r0, r1, r2, r3, addr) \
    asm volatile("ldmatrix.sync.aligned.m8n8.x4.shared.b16 {%0,%1,%2,%3},[%4];" \
                 : "=r"(r0), "=r"(r1), "=r"(r2), "=r"(r3) : "r"(addr))

#define LDSM4T(r0, r1, r2, r3, addr) \
    asm volatile("ldmatrix.sync.aligned.m8n8.x4.trans.shared.b16 {%0,%1,%2,%3},[%4];" \
                 : "=r"(r0), "=r"(r1), "=r"(r2), "=r"(r3) : "r"(addr))

#define MMA16816(c, a, b0, b1) \
    asm volatile("mma.sync.aligned.m16n8k16.row.col.f32.bf16.bf16.f32 " \
                 "{%0,%1,%2,%3},{%4,%5,%6,%7},{%8,%9},{%0,%1,%2,%3};" \
                 : "+f"((c)[0]), "+f"((c)[1]), "+f"((c)[2]), "+f"((c)[3]) \
                 : "r"((a)[0]), "r"((a)[1]), "r"((a)[2]), "r"((a)[3]), "r"(b0), "r"(b1))

// =====================================================================
// bgemm: tensor-core GEMM with 2-term bf16 split (hi*hi + hi*mid + mid*hi).
// C[M,N] = concat_K(A0|A1) @ B + bias + cs*Cin, optional relu.
// Seg [0,kb1) -> A0 (gather r0a), [kb1,K) -> A1 (gather r1a).
// Dual mode (gridDim.z==2): z==1 swaps gathers, writes C_dual.
// Requirements: M%128==0, N%128==0, K%32==0, kb1%32==0, ldb==N,
// A pointers 16B aligned, lda%4==0.
// Block tile 128x128x32; 8 warps = 4(m) x 2(n); warp tile 32x64.
// =====================================================================
__global__ __launch_bounds__(256, 2) void bgemm_kernel(
    const float* __restrict__ A0, int lda0, const int* __restrict__ r0a,
    const float* __restrict__ A1, int lda1, const int* __restrict__ r1a,
    int kb1,
    const float* __restrict__ B,
    const float* __restrict__ bias,
    const float* __restrict__ Cin, int ldcin, float cs,
    float* __restrict__ C, float* __restrict__ C_dual, int ldc,
    int Ndim, int Kdim, int relu)
{
    __shared__ __align__(16) __nv_bfloat16 Ah[128][40];
    __shared__ __align__(16) __nv_bfloat16 Am[128][40];
    __shared__ __align__(16) __nv_bfloat16 Bh[32][136];
    __shared__ __align__(16) __nv_bfloat16 Bm[32][136];
    __shared__ int rows0[128], rows1[128];

    const int tid = threadIdx.x;
    const int lane = tid & 31;
    const int wid = tid >> 5;
    const int warp_m = wid >> 1;   // 0..3
    const int warp_n = wid & 1;    // 0..1
    const int row0 = blockIdx.y * 128;
    const int col0 = blockIdx.x * 128;

    const int* g0 = r0a;
    const int* g1 = r1a;
    float* Cout = C;
    if (blockIdx.z == 1) { g0 = r1a; g1 = r0a; Cout = C_dual; }

    if (tid < 128) {
        rows0[tid] = g0 ? __ldg(&g0[row0 + tid]) : (row0 + tid);
        rows1[tid] = g1 ? __ldg(&g1[row0 + tid]) : (row0 + tid);
    }
    __syncthreads();

    float acc[2][8][4];
#pragma unroll
    for (int i = 0; i < 2; i++)
#pragma unroll
        for (int j = 0; j < 8; j++)
#pragma unroll
            for (int l = 0; l < 4; l++) acc[i][j][l] = 0.f;

    for (int k0 = 0; k0 < Kdim; k0 += 32) {
        const float* Ap; int lda; const int* rs; int kloc;
        if (k0 < kb1) { Ap = A0; lda = lda0; rs = rows0; kloc = k0; }
        else { Ap = A1; lda = lda1; rs = rows1; kloc = k0 - kb1; }

        // ---- A tile fill: 128 rows x 32 k, split to hi/mid bf16 ----
#pragma unroll
        for (int u = 0; u < 4; u++) {
            int idx = tid + u * 256;
            int m = idx >> 3;
            int kq = (idx & 7) << 2;
            int ar = rs[m];
            float4 v = *(const float4*)(Ap + (size_t)ar * lda + kloc + kq);
            __nv_bfloat16 h0 = __float2bfloat16(v.x);
            __nv_bfloat16 h1 = __float2bfloat16(v.y);
            __nv_bfloat16 h2 = __float2bfloat16(v.z);
            __nv_bfloat16 h3 = __float2bfloat16(v.w);
            __nv_bfloat16 m0 = __float2bfloat16(v.x - __bfloat162float(h0));
            __nv_bfloat16 m1 = __float2bfloat16(v.y - __bfloat162float(h1));
            __nv_bfloat16 m2 = __float2bfloat16(v.z - __bfloat162float(h2));
            __nv_bfloat16 m3 = __float2bfloat16(v.w - __bfloat162float(h3));
            __nv_bfloat162* ph = (__nv_bfloat162*)&Ah[m][kq];
            ph[0] = __nv_bfloat162(h0, h1);
            ph[1] = __nv_bfloat162(h2, h3);
            __nv_bfloat162* pm = (__nv_bfloat162*)&Am[m][kq];
            pm[0] = __nv_bfloat162(m0, m1);
            pm[1] = __nv_bfloat162(m2, m3);
        }
        // ---- B tile fill: 32 k x 128 n ----
#pragma unroll
        for (int u = 0; u < 4; u++) {
            int idx = tid + u * 256;
            int kk = idx >> 5;
            int nq = (idx & 31) << 2;
            float4 v = *(const float4*)(B + (size_t)(k0 + kk) * Ndim + col0 + nq);
            __nv_bfloat16 h0 = __float2bfloat16(v.x);
            __nv_bfloat16 h1 = __float2bfloat16(v.y);
            __nv_bfloat16 h2 = __float2bfloat16(v.z);
            __nv_bfloat16 h3 = __float2bfloat16(v.w);
            __nv_bfloat16 m0 = __float2bfloat16(v.x - __bfloat162float(h0));
            __nv_bfloat16 m1 = __float2bfloat16(v.y - __bfloat162float(h1));
            __nv_bfloat16 m2 = __float2bfloat16(v.z - __bfloat162float(h2));
            __nv_bfloat16 m3 = __float2bfloat16(v.w - __bfloat162float(h3));
            __nv_bfloat162* ph = (__nv_bfloat162*)&Bh[kk][nq];
            ph[0] = __nv_bfloat162(h0, h1);
            ph[1] = __nv_bfloat162(h2, h3);
            __nv_bfloat162* pm = (__nv_bfloat162*)&Bm[kk][nq];
            pm[0] = __nv_bfloat162(m0, m1);
            pm[1] = __nv_bfloat162(m2, m3);
        }
        __syncthreads();

#pragma unroll
        for (int h = 0; h < 2; h++) {  // two k16 halves of BK=32
            const int kh = h * 16;
            uint32_t ah[2][4], am[2][4];
#pragma unroll
            for (int mt = 0; mt < 2; mt++) {
                int r = warp_m * 32 + mt * 16 + (lane & 15);
                int kc = kh + ((lane >> 4) << 3);
                uint32_t addr = s2u(&Ah[r][kc]);
                LDSM4(ah[mt][0], ah[mt][1], ah[mt][2], ah[mt][3], addr);
                addr = s2u(&Am[r][kc]);
                LDSM4(am[mt][0], am[mt][1], am[mt][2], am[mt][3], addr);
            }
#pragma unroll
            for (int p = 0; p < 4; p++) {  // n-tile pairs (16 cols each)
                uint32_t bh[4], bm[4];
                int kr = kh + (lane & 15);
                int cb = warp_n * 64 + p * 16 + ((lane >> 4) << 3);
                uint32_t addr = s2u(&Bh[kr][cb]);
                LDSM4T(bh[0], bh[1], bh[2], bh[3], addr);
                addr = s2u(&Bm[kr][cb]);
                LDSM4T(bm[0], bm[1], bm[2], bm[3], addr);
#pragma unroll
                for (int mt = 0; mt < 2; mt++) {
                    MMA16816(acc[mt][p * 2 + 0], ah[mt], bh[0], bh[1]);
                    MMA16816(acc[mt][p * 2 + 0], ah[mt], bm[0], bm[1]);
                    MMA16816(acc[mt][p * 2 + 0], am[mt], bh[0], bh[1]);
                    MMA16816(acc[mt][p * 2 + 1], ah[mt], bh[2], bh[3]);
                    MMA16816(acc[mt][p * 2 + 1], ah[mt], bm[2], bm[3]);
                    MMA16816(acc[mt][p * 2 + 1], am[mt], bh[2], bh[3]);
                }
            }
        }
        __syncthreads();
    }

    // ---- epilogue ----
    const int rbase = row0 + warp_m * 32 + (lane >> 2);
    const int cbase = col0 + warp_n * 64 + (lane & 3) * 2;
#pragma unroll
    for (int mt = 0; mt < 2; mt++) {
#pragma unroll
        for (int hf = 0; hf < 2; hf++) {
            int r = rbase + mt * 16 + hf * 8;
            float* crow = Cout + (size_t)r * ldc;
            const float* cinr = Cin ? (Cin + (size_t)r * ldcin) : nullptr;
#pragma unroll
            for (int nt = 0; nt < 8; nt++) {
                int c = cbase + nt * 8;
                float v0 = acc[mt][nt][hf * 2 + 0];
                float v1 = acc[mt][nt][hf * 2 + 1];
                if (bias) { v0 += __ldg(&bias[c]); v1 += __ldg(&bias[c + 1]); }
                if (cinr) { v0 += cs * cinr[c]; v1 += cs * cinr[c + 1]; }
                if (relu) { v0 = fmaxf(v0, 0.f); v1 = fmaxf(v1, 0.f); }
                crow[c] = v0;
                crow[c + 1] = v1;
            }
        }
    }
}

// ---------------- misc elementwise ----------------
__global__ void zero_kernel(float* __restrict__ p, size_t n) {
    size_t i = (size_t)blockIdx.x * blockDim.x + threadIdx.x;
    size_t stride = (size_t)gridDim.x * blockDim.x;
    for (; i < n; i += stride) p[i] = 0.f;
}

__global__ void wab_kernel(const float* __restrict__ msgW, float* __restrict__ wab) {
    int i = blockIdx.x * blockDim.x + threadIdx.x;
    if (i < 128 * 256) wab[i] = msgW[i] + msgW[128 * 256 + i];
}

// sumsd[e][0:128] = hn[from[e]] + hn[to[e]]  (hn stride 768), float4
__global__ void sumsd_kernel(const float* __restrict__ hn, const int* __restrict__ from_idx,
                             const int* __restrict__ to_idx, float* __restrict__ out)
{
    int i = blockIdx.x * blockDim.x + threadIdx.x;
    if (i >= VE * 32) return;
    int e = i >> 5;
    int c4 = (i & 31) << 2;
    const float4 a = *(const float4*)(hn + (size_t)from_idx[e] * 768 + c4);
    const float4 b = *(const float4*)(hn + (size_t)to_idx[e] * 768 + c4);
    float4 o;
    o.x = a.x + b.x; o.y = a.y + b.y; o.z = a.z + b.z; o.w = a.w + b.w;
    *(float4*)(out + (size_t)e * 128 + c4) = o;
}

// ---------------- message aggregation scatter ----------------
__global__ void scatter_add_kernel(const float* __restrict__ fwd, const float* __restrict__ bwd,
                                   const int* __restrict__ from_idx, const int* __restrict__ to_idx,
                                   float* __restrict__ agg)
{
    size_t i = (size_t)blockIdx.x * blockDim.x + threadIdx.x;
    if (i >= (size_t)VE * 256) return;
    int e = (int)(i >> 8);
    int c = (int)(i & 255);
    atomicAdd(&agg[(size_t)to_idx[e] * 256 + c], fwd[i]);
    atomicAdd(&agg[(size_t)from_idx[e] * 256 + c], bwd[i]);
}

// ---------------- transport MLP (fdim -> 64 -> 64, pad rows zero) ----------------
__global__ void transport_mlp_kernel(const float* __restrict__ upd, int ld, int foff, int fdim,
                                     const float* __restrict__ W1, const float* __restrict__ b1,
                                     const float* __restrict__ W2, const float* __restrict__ b2,
                                     float* __restrict__ tout, int maxr, int nreal)
{
    int i = blockIdx.x;
    int g = blockIdx.y;
    int j = threadIdx.x;
    size_t outoff = ((size_t)g * maxr + i) * 64 + j;
    if (i >= nreal) { tout[outoff] = 0.f; return; }
    __shared__ float f[256];
    __shared__ float hid[64];
    const float* frow = upd + ((size_t)g * nreal + i) * ld + foff;
    for (int k = j; k < fdim; k += 64) f[k] = frow[k];
    __syncthreads();
    float h = b1[j];
    for (int k = 0; k < fdim; k++) h += f[k] * W1[k * 64 + j];
    hid[j] = fmaxf(h, 0.f);
    __syncthreads();
    float o = b2[j];
#pragma unroll
    for (int k = 0; k < 64; k++) o += hid[k] * W2[k * 64 + j];
    tout[outoff] = o;
}

// ---------------- la = (tq @ tc^T) / TEMP ----------------
__global__ void la_kernel(const float* __restrict__ t, float* __restrict__ la, int maxr)
{
    __shared__ float Tq[16][65];
    __shared__ float Tc[16][65];
    int b = blockIdx.z;
    int q0 = blockIdx.y * 16;
    int c0 = blockIdx.x * 16;
    const float* tq = t + (size_t)(2 * b) * maxr * 64;
    const float* tc = t + (size_t)(2 * b + 1) * maxr * 64;
    int ty = threadIdx.y, tx = threadIdx.x;
    int lin = ty * 16 + tx;
#pragma unroll
    for (int u = 0; u < 4; u++) {
        int idx = lin + u * 256;
        int r = idx / 64, k = idx % 64;
        Tq[r][k] = tq[(size_t)(q0 + r) * 64 + k];
        Tc[r][k] = tc[(size_t)(c0 + r) * 64 + k];
    }
    __syncthreads();
    float s = 0.f;
#pragma unroll
    for (int k = 0; k < 64; k++) s += Tq[ty][k] * Tc[tx][k];
    la[((size_t)b * maxr + q0 + ty) * maxr + c0 + tx] = s * INV_TEMP;
}

// ---------------- fused node Sinkhorn: smem-resident 64x64, 10 iters + exp
__global__ __launch_bounds__(256) void node_sink_kernel(float* __restrict__ la)
{
    __shared__ float L[64][65];
    float* base = la + (size_t)blockIdx.x * 4096;
    int tid = threadIdx.x;
    for (int i = tid; i < 4096; i += 256) L[i >> 6][i & 63] = base[i];
    __syncthreads();
    int r = tid >> 2;
    int part = (tid & 3) * 16;
    for (int iter = 0; iter < SINK_ITERS; iter++) {
        {
            float m = -INFINITY;
#pragma unroll
            for (int i = 0; i < 16; i++) m = fmaxf(m, L[r][part + i]);
            m = fmaxf(m, __shfl_xor_sync(0xFFFFFFFFu, m, 1));
            m = fmaxf(m, __shfl_xor_sync(0xFFFFFFFFu, m, 2));
            float s = 0.f;
#pragma unroll
            for (int i = 0; i < 16; i++) s += expf(L[r][part + i] - m);
            s += __shfl_xor_sync(0xFFFFFFFFu, s, 1);
            s += __shfl_xor_sync(0xFFFFFFFFu, s, 2);
            float lse = m + logf(s);
#pragma unroll
            for (int i = 0; i < 16; i++) L[r][part + i] -= lse;
        }
        __syncthreads();
        {
            float m = -INFINITY;
#pragma unroll
            for (int i = 0; i < 16; i++) m = fmaxf(m, L[part + i][r]);
            m = fmaxf(m, __shfl_xor_sync(0xFFFFFFFFu, m, 1));
            m = fmaxf(m, __shfl_xor_sync(0xFFFFFFFFu, m, 2));
            float s = 0.f;
#pragma unroll
            for (int i = 0; i < 16; i++) s += expf(L[part + i][r] - m);
            s += __shfl_xor_sync(0xFFFFFFFFu, s, 1);
            s += __shfl_xor_sync(0xFFFFFFFFu, s, 2);
            float lse = m + logf(s);
#pragma unroll
            for (int i = 0; i < 16; i++) L[part + i][r] -= lse;
        }
        __syncthreads();
    }
    for (int i = tid; i < 4096; i += 256) base[i] = expf(L[i >> 6][i & 63]);
}

// ---------------- fused edge Sinkhorn: 256x256, 10 iters + exp
__global__ __launch_bounds__(1024) void edge_sink_kernel(float* __restrict__ la)
{
    float* base = la + (size_t)blockIdx.x * 65536;
    int tid = threadIdx.x;
    int wid = tid >> 5, lane = tid & 31;
    __shared__ float cr[4][256];
    int c = tid & 255, g = tid >> 8;
    for (int iter = 0; iter < SINK_ITERS; iter++) {
        for (int r = wid; r < 256; r += 32) {
            float* rp = base + (size_t)r * 256;
            float4 v0 = *(float4*)(rp + lane * 4);
            float4 v1 = *(float4*)(rp + 128 + lane * 4);
            float m = fmaxf(fmaxf(fmaxf(v0.x, v0.y), fmaxf(v0.z, v0.w)),
                            fmaxf(fmaxf(v1.x, v1.y), fmaxf(v1.z, v1.w)));
#pragma unroll
            for (int o = 16; o > 0; o >>= 1) m = fmaxf(m, __shfl_xor_sync(0xFFFFFFFFu, m, o));
            float s = expf(v0.x - m) + expf(v0.y - m) + expf(v0.z - m) + expf(v0.w - m)
                    + expf(v1.x - m) + expf(v1.y - m) + expf(v1.z - m) + expf(v1.w - m);
#pragma unroll
            for (int o = 16; o > 0; o >>= 1) s += __shfl_xor_sync(0xFFFFFFFFu, s, o);
            float lse = m + logf(s);
            v0.x -= lse; v0.y -= lse; v0.z -= lse; v0.w -= lse;
            v1.x -= lse; v1.y -= lse; v1.z -= lse; v1.w -= lse;
            *(float4*)(rp + lane * 4) = v0;
            *(float4*)(rp + 128 + lane * 4) = v1;
        }
        __syncthreads();
        float m = -INFINITY;
        for (int r = g * 64; r < g * 64 + 64; r++) m = fmaxf(m, base[(size_t)r * 256 + c]);
        cr[g][c] = m;
        __syncthreads();
        if (g == 0) cr[0][c] = fmaxf(fmaxf(cr[0][c], cr[1][c]), fmaxf(cr[2][c], cr[3][c]));
        __syncthreads();
        m = cr[0][c];
        float s = 0.f;
        for (int r = g * 64; r < g * 64 + 64; r++) s += expf(base[(size_t)r * 256 + c] - m);
        __syncthreads();
        cr[g][c] = s;
        __syncthreads();
        if (g == 0) cr[0][c] = m + logf(cr[0][c] + cr[1][c] + cr[2][c] + cr[3][c]);
        __syncthreads();
        float lse = cr[0][c];
        bool last = (iter == SINK_ITERS - 1);
        for (int r = g * 64; r < g * 64 + 64; r++) {
            float v = base[(size_t)r * 256 + c] - lse;
            base[(size_t)r * 256 + c] = last ? expf(v) : v;
        }
        __syncthreads();
    }
}

// ---------------- plan apply ----------------
#define GBM 64
#define GBN 64
#define GBK 16
__global__ __launch_bounds__(256) void trans_apply_kernel(
    const float* __restrict__ plan, const float* __restrict__ upd,
    float* __restrict__ store, int maxr, int nreal, int ld, int coff)
{
    __shared__ float Ps[GBK][GBM];
    __shared__ float Fs[GBK][GBN];
    int z = blockIdx.z;
    int b = z >> 1;
    int mode = z & 1;
    const float* P = plan + (size_t)b * maxr * maxr;
    int fgrp = 2 * b + (mode ? 0 : 1);
    int ogrp = 2 * b + mode;
    const float* F = upd + (size_t)fgrp * nreal * ld + coff;
    float* C = store + (size_t)ogrp * nreal * ld + coff;
    int ncols = ld - coff;
    int block_row = blockIdx.y * GBM;
    int block_col = blockIdx.x * GBN;
    int tid = threadIdx.x;
    float acc[4][4];
#pragma unroll
    for (int i = 0; i < 4; i++)
#pragma unroll
        for (int j = 0; j < 4; j++) acc[i][j] = 0.f;
    int tr = (tid / 16) * 4;
    int tc = (tid % 16) * 4;

    for (int k0 = 0; k0 < nreal; k0 += GBK) {
#pragma unroll
        for (int u = 0; u < 4; u++) {
            int idx = tid + u * 256;
            int m = idx / GBK;
            int k = idx % GBK;
            int gr = block_row + m;
            int gk = k0 + k;
            float v = 0.f;
            if (gr < nreal && gk < nreal)
                v = mode ? P[(size_t)gk * maxr + gr] : P[(size_t)gr * maxr + gk];
            Ps[k][m] = v;
        }
#pragma unroll
        for (int u = 0; u < 4; u++) {
            int idx = tid + u * 256;
            int k = idx / GBN;
            int n = idx % GBN;
            int gk = k0 + k;
            int gn = block_col + n;
            float v = 0.f;
            if (gk < nreal && gn < ncols) v = F[(size_t)gk * ld + gn];
            Fs[k][n] = v;
        }
        __syncthreads();
#pragma unroll
        for (int k = 0; k < GBK; k++) {
            float a0 = Ps[k][tr], a1 = Ps[k][tr + 1], a2 = Ps[k][tr + 2], a3 = Ps[k][tr + 3];
            float b0 = Fs[k][tc], b1 = Fs[k][tc + 1], b2 = Fs[k][tc + 2], b3 = Fs[k][tc + 3];
            acc[0][0] += a0 * b0; acc[0][1] += a0 * b1; acc[0][2] += a0 * b2; acc[0][3] += a0 * b3;
            acc[1][0] += a1 * b0; acc[1][1] += a1 * b1; acc[1][2] += a1 * b2; acc[1][3] += a1 * b3;
            acc[2][0] += a2 * b0; acc[2][1] += a2 * b1; acc[2][2] += a2 * b2; acc[2][3] += a2 * b3;
            acc[3][0] += a3 * b0; acc[3][1] += a3 * b1; acc[3][2] += a3 * b2; acc[3][3] += a3 * b3;
        }
        __syncthreads();
    }

#pragma unroll
    for (int i = 0; i < 4; i++) {
        int r = block_row + tr + i;
        if (r >= nreal) continue;
#pragma unroll
        for (int j = 0; j < 4; j++) {
            int c = block_col + tc + j;
            if (c >= ncols) continue;
            C[(size_t)r * ld + c] = acc[i][j];
        }
    }
}

// ---------------- score ----------------
__global__ void score_kernel(const float* __restrict__ upd_node, const float* __restrict__ plan,
                             float* __restrict__ out)
{
    int b = blockIdx.x;
    int t = threadIdx.x;
    __shared__ float P[64][64];
    __shared__ float FC[48][128];
    __shared__ float red[128];
    for (int idx = t; idx < 64 * 64; idx += 128)
        P[idx / 64][idx % 64] = plan[(size_t)b * 4096 + idx];
    for (int idx = t; idx < 48 * 128; idx += 128) {
        int c = idx / 128, d = idx % 128;
        FC[c][d] = upd_node[((size_t)(2 * b + 1) * 48 + c) * 768 + 640 + d];
    }
    __syncthreads();
    float acc = 0.f;
    for (int q = 0; q < 64; q++) {
        float s = 0.f;
#pragma unroll 8
        for (int c = 0; c < 48; c++) s += P[q][c] * FC[c][t];
        float fq = 0.f;
        if (q < 48) fq = upd_node[((size_t)(2 * b) * 48 + q) * 768 + 640 + t];
        acc += fmaxf(fq - s, 0.f);
    }
    red[t] = acc;
    __syncthreads();
    for (int s2 = 64; s2 > 0; s2 >>= 1) {
        if (t < s2) red[t] += red[t + s2];
        __syncthreads();
    }
    if (t == 0) out[b] = -red[0];
}

// ---------------- host helpers ----------------
struct Seg { const float* A; int lda; const int* rows; };

static void bgemm(Seg s0, Seg s1, int kb1,
                  const float* B, const float* bias,
                  const float* Cin, int ldcin, float cs,
                  float* C, float* Cd, int ldc, int M, int N, int K, int relu, int dual)
{
    dim3 g(N / 128, M / 128, dual ? 2 : 1);
    bgemm_kernel<<<g, 256>>>(s0.A, s0.lda, s0.rows, s1.A, s1.lda, s1.rows, kb1,
                             B, bias, Cin, ldcin, cs, C, Cd, ldc, N, K, relu);
}

static void zero_buf(float* p, size_t n)
{
    int grid = (int)((n + 255) / 256);
    if (grid > 8192) grid = 8192;
    zero_kernel<<<grid, 256>>>(p, n);
}

extern "C" void kernel_launch(void* const* d_in, const int* in_sizes, int n_in,
                              void* d_out, int out_size)
{
    const float* node_features = (const float*)d_in[0];
    const float* edge_features = (const float*)d_in[1];
    const int* from_idx = (const int*)d_in[2];
    const int* to_idx = (const int*)d_in[3];
    const float* enc_node_W = (const float*)d_in[4];
    const float* enc_node_b = (const float*)d_in[5];
    const float* enc_edge_W = (const float*)d_in[6];
    const float* enc_edge_b = (const float*)d_in[7];
    const float* ni_W1 = (const float*)d_in[8];
    const float* ni_b1 = (const float*)d_in[9];
    const float* ni_W2 = (const float*)d_in[10];
    const float* ni_b2 = (const float*)d_in[11];
    const float* ei_W1 = (const float*)d_in[12];
    const float* ei_b1 = (const float*)d_in[13];
    const float* ei_W2 = (const float*)d_in[14];
    const float* ei_b2 = (const float*)d_in[15];
    const float* msg_W = (const float*)d_in[16];
    const float* msg_b = (const float*)d_in[17];
    const float* nu_W1 = (const float*)d_in[18];
    const float* nu_b1 = (const float*)d_in[19];
    const float* nu_W2 = (const float*)d_in[20];
    const float* nu_b2 = (const float*)d_in[21];
    const float* ns_W1 = (const float*)d_in[22];
    const float* ns_b1 = (const float*)d_in[23];
    const float* ns_W2 = (const float*)d_in[24];
    const float* ns_b2 = (const float*)d_in[25];
    const float* es_W1 = (const float*)d_in[26];
    const float* es_b1 = (const float*)d_in[27];
    const float* es_W2 = (const float*)d_in[28];
    const float* es_b2 = (const float*)d_in[29];

    float* S = nullptr;
    cudaGetSymbolAddress((void**)&S, g_scratch);

    float* enc_n = S + OFF_ENC_N;
    float* enc_e = S + OFF_ENC_E;
    float* node_store = S + OFF_NS;
    float* edge_store = S + OFF_ES;
    float* UN = S + OFF_UN;
    float* UE = S + OFF_UE;
    float* tmpN = S + OFF_TMPN;
    float* tmpE = S + OFF_TMPE;
    float* hcomb = S + OFF_HC;
    float* ecomb = S + OFF_EC;
    float* fwd = S + OFF_FWD;
    float* bwd = S + OFF_BWD;
    float* agg = S + OFF_AGG;
    float* TN = S + OFF_TN;
    float* TE = S + OFF_TE;
    float* PLN = S + OFF_PLN;
    float* PLE = S + OFF_PLE;
    float* ewc = S + OFF_EWC;
    float* wab = S + OFF_WAB;

    Seg none{nullptr, 0, nullptr};

    // one-time zeroing (transport fully overwrites the read regions each K)
    zero_buf(node_store, SZ_NS);
    zero_buf(edge_store, SZ_ES);
    wab_kernel<<<(128 * 256 + 255) / 256, 256>>>(msg_W, wab);

    // encoders (K=32)
    bgemm(Seg{node_features, DIN, nullptr}, none, 32,
          enc_node_W, enc_node_b, nullptr, 0, 0.f, enc_n, nullptr, 128, VN, 128, 32, 0, 0);
    bgemm(Seg{edge_features, DIN, nullptr}, none, 32,
          enc_edge_W, enc_edge_b, nullptr, 0, 0.f, enc_e, nullptr, 128, VE, 128, 32, 0, 0);

    for (int k = 0; k < KK; k++) {
        for (int p = 1; p <= TT; p++) {
            const float* hptr = (p == 1) ? enc_n : (UN + (size_t)(p - 1) * 128);
            int hlda = (p == 1) ? 128 : 768;

            // h_comb = mlp2([h | node_store slice], ni)
            bgemm(Seg{hptr, hlda, nullptr},
                  Seg{node_store + (size_t)(p - 1) * 128, 768, nullptr}, 128,
                  ni_W1, ni_b1, nullptr, 0, 0.f, tmpN, nullptr, 256, VN, 256, 256, 1, 0);
            bgemm(Seg{tmpN, 256, nullptr}, none, 256,
                  ni_W2, ni_b2, nullptr, 0, 0.f, hcomb, nullptr, 128, VN, 128, 256, 0, 0);

            // e_comb = mlp2([enc_e | edge_store slice], ei)
            bgemm(Seg{enc_e, 128, nullptr},
                  Seg{edge_store + (size_t)(p - 1) * 256, 1536, nullptr}, 128,
                  ei_W1, ei_b1, nullptr, 0, 0.f, tmpE, nullptr, 384, VE, 384, 384, 1, 0);
            bgemm(Seg{tmpE, 384, nullptr}, none, 384,
                  ei_W2, ei_b2, nullptr, 0, 0.f, ecomb, nullptr, 128, VE, 128, 384, 0, 0);

            // EWc = ecomb @ msg_W[256:384] + msg_b
            bgemm(Seg{ecomb, 128, nullptr}, none, 128,
                  msg_W + 256 * 256, msg_b, nullptr, 0, 0.f, ewc, nullptr, 256, VE, 256, 128, 0, 0);

            // fwd & bwd in ONE dual launch:
            //   fwd = [h_comb[from] | h_comb[to]] @ msg_W[0:256] + EWc
            bgemm(Seg{hcomb, 128, from_idx}, Seg{hcomb, 128, to_idx}, 128,
                  msg_W, nullptr, ewc, 256, 1.f, fwd, bwd, 256, VE, 256, 256, 0, 1);

            // aggregate
            zero_buf(agg, SZ_AGG);
            {
                size_t tot = (size_t)VE * 256;
                int grid = (int)((tot + 255) / 256);
                scatter_add_kernel<<<grid, 256>>>(fwd, bwd, from_idx, to_idx, agg);
            }

            // h_new = mlp2([h_comb | agg], nu) -> UN slot p
            bgemm(Seg{hcomb, 128, nullptr}, Seg{agg, 256, nullptr}, 128,
                  nu_W1, nu_b1, nullptr, 0, 0.f, tmpN, nullptr, 256, VN, 256, 384, 1, 0);
            bgemm(Seg{tmpN, 256, nullptr}, none, 256,
                  nu_W2, nu_b2, nullptr, 0, 0.f, UN + (size_t)p * 128, nullptr, 768, VN, 128, 256, 0, 0);

            // msgs2 = (h[from]+h[to]) @ (Wa+Wb) + 2*EWc -> UE slot p
            const float* hn = UN + (size_t)p * 128;
            sumsd_kernel<<<(VE * 32 + 255) / 256, 256>>>(hn, from_idx, to_idx, tmpE);
            bgemm(Seg{tmpE, 128, nullptr}, none, 128,
                  wab, nullptr, ewc, 256, 2.f, UE + (size_t)p * 256, nullptr, 1536, VE, 256, 128, 0, 0);
        }

        // ----- node transport -----
        transport_mlp_kernel<<<dim3(MAXN, NGRP), 64>>>(UN, 768, 640, 128, ns_W1, ns_b1,
                                                       ns_W2, ns_b2, TN, MAXN, NPER);
        la_kernel<<<dim3(4, 4, BNUM), dim3(16, 16)>>>(TN, PLN, MAXN);
        node_sink_kernel<<<BNUM, 256>>>(PLN);
        trans_apply_kernel<<<dim3(10, 1, NGRP), 256>>>(PLN, UN, node_store, MAXN, NPER, 768, 128);

        // ----- edge transport -----
        transport_mlp_kernel<<<dim3(MAXE, NGRP), 64>>>(UE, 1536, 1280, 256, es_W1, es_b1,
                                                       es_W2, es_b2, TE, MAXE, EPER);
        la_kernel<<<dim3(16, 16, BNUM), dim3(16, 16)>>>(TE, PLE, MAXE);
        edge_sink_kernel<<<BNUM, 1024>>>(PLE);
        trans_apply_kernel<<<dim3(20, 3, NGRP), 256>>>(PLE, UE, edge_store, MAXE, EPER, 1536, 256);
    }

    // ----- score -----
    score_kernel<<<BNUM, 128>>>(UN, PLN, (float*)d_out);
}

// round 10
// speedup vs baseline: 3.7830x; 1.2451x over previous
#include <cuda_runtime.h>
#include <cuda_bf16.h>
#include <math.h>
#include <stdint.h>

// ---------------- constants ----------------
#define BNUM 64
#define NGRP 128
#define NPER 48
#define EPER 192
#define MAXN 64
#define MAXE 256
#define DIN 32
#define TT 5
#define KK 3
#define VN 6144
#define VE 24576
#define INV_TEMP 10.0f
#define SINK_ITERS 10

// ---------------- scratch layout (floats) ----------------
#define SZ_ENC_N ((size_t)VN * 128)
#define SZ_ENC_E ((size_t)VE * 128)
#define SZ_NS ((size_t)VN * 768)
#define SZ_ES ((size_t)VE * 1536)
#define SZ_UN ((size_t)VN * 768)
#define SZ_UE ((size_t)VE * 1536)
#define SZ_TMPN ((size_t)VN * 256)
#define SZ_TMPE ((size_t)VE * 384)
#define SZ_HC ((size_t)VN * 128)
#define SZ_EC ((size_t)VE * 128)
#define SZ_FWD ((size_t)VE * 256)
#define SZ_AGG ((size_t)VN * 256)
#define SZ_TN ((size_t)NGRP * 64 * 64)
#define SZ_TE ((size_t)NGRP * 256 * 64)
#define SZ_PLN ((size_t)BNUM * 64 * 64)
#define SZ_PLE ((size_t)BNUM * 256 * 256)
#define SZ_EWC ((size_t)VE * 256)
#define SZ_WAB ((size_t)128 * 256)
#define SZ_CSR ((size_t)(3 * VN + 2 + 2 * VE))

#define OFF_ENC_N ((size_t)0)
#define OFF_ENC_E (OFF_ENC_N + SZ_ENC_N)
#define OFF_NS (OFF_ENC_E + SZ_ENC_E)
#define OFF_ES (OFF_NS + SZ_NS)
#define OFF_UN (OFF_ES + SZ_ES)
#define OFF_UE (OFF_UN + SZ_UN)
#define OFF_TMPN (OFF_UE + SZ_UE)
#define OFF_TMPE (OFF_TMPN + SZ_TMPN)
#define OFF_HC (OFF_TMPE + SZ_TMPE)
#define OFF_EC (OFF_HC + SZ_HC)
#define OFF_FWD (OFF_EC + SZ_EC)
#define OFF_BWD (OFF_FWD + SZ_FWD)
#define OFF_AGG (OFF_BWD + SZ_FWD)
#define OFF_TN (OFF_AGG + SZ_AGG)
#define OFF_TE (OFF_TN + SZ_TN)
#define OFF_PLN (OFF_TE + SZ_TE)
#define OFF_PLE (OFF_PLN + SZ_PLN)
#define OFF_EWC (OFF_PLE + SZ_PLE)
#define OFF_WAB (OFF_EWC + SZ_EWC)
#define OFF_CSR (OFF_WAB + SZ_WAB)
#define SCRATCH_TOTAL (OFF_CSR + SZ_CSR)

__device__ float g_scratch[SCRATCH_TOTAL];

// ---------------- mma helpers ----------------
__device__ __forceinline__ uint32_t s2u(const void* p) {
    return (uint32_t)__cvta_generic_to_shared(p);
}

#define LDSM4(r0, r1, r2, r3, addr) \
    asm volatile("ldmatrix.sync.aligned.m8n8.x4.shared.b16 {%0,%1,%2,%3},[%4];" \
                 : "=r"(r0), "=r"(r1), "=r"(r2), "=r"(r3) : "r"(addr))

#define LDSM4T(r0, r1, r2, r3, addr) \
    asm volatile("ldmatrix.sync.aligned.m8n8.x4.trans.shared.b16 {%0,%1,%2,%3},[%4];" \
                 : "=r"(r0), "=r"(r1), "=r"(r2), "=r"(r3) : "r"(addr))

#define MMA16816(c, a, b0, b1) \
    asm volatile("mma.sync.aligned.m16n8k16.row.col.f32.bf16.bf16.f32 " \
                 "{%0,%1,%2,%3},{%4,%5,%6,%7},{%8,%9},{%0,%1,%2,%3};" \
                 : "+f"((c)[0]), "+f"((c)[1]), "+f"((c)[2]), "+f"((c)[3]) \
                 : "r"((a)[0]), "r"((a)[1]), "r"((a)[2]), "r"((a)[3]), "r"(b0), "r"(b1))

__device__ __forceinline__ void split_store4(__nv_bfloat16* ph, __nv_bfloat16* pm, float4 v)
{
    __nv_bfloat16 h0 = __float2bfloat16(v.x);
    __nv_bfloat16 h1 = __float2bfloat16(v.y);
    __nv_bfloat16 h2 = __float2bfloat16(v.z);
    __nv_bfloat16 h3 = __float2bfloat16(v.w);
    ((__nv_bfloat162*)ph)[0] = __nv_bfloat162(h0, h1);
    ((__nv_bfloat162*)ph)[1] = __nv_bfloat162(h2, h3);
    ((__nv_bfloat162*)pm)[0] = __nv_bfloat162(__float2bfloat16(v.x - __bfloat162float(h0)),
                                              __float2bfloat16(v.y - __bfloat162float(h1)));
    ((__nv_bfloat162*)pm)[1] = __nv_bfloat162(__float2bfloat16(v.z - __bfloat162float(h2)),
                                              __float2bfloat16(v.w - __bfloat162float(h3)));
}

// =====================================================================
// bgemm<BM>: tensor-core GEMM, 2-term bf16 split (hi*hi + hi*mid + mid*hi).
// C[M,N] = concat_K(A0|A1) @ B + bias + cs*Cin, optional relu.
// BM=128: 8 warps 4x2 (warp 32x64). BM=64: 8 warps 2x4 (warp 32x32).
// Dual mode (gridDim.z==2): z==1 swaps gathers, writes C_dual.
// M%BM==0, N%128==0, K%32==0, kb1%32==0, ldb==N, 16B alignment.
// =====================================================================
template <int BM>
__global__ __launch_bounds__(256, 2) void bgemm_kernel(
    const float* __restrict__ A0, int lda0, const int* __restrict__ r0a,
    const float* __restrict__ A1, int lda1, const int* __restrict__ r1a,
    int kb1,
    const float* __restrict__ B,
    const float* __restrict__ bias,
    const float* __restrict__ Cin, int ldcin, float cs,
    float* __restrict__ C, float* __restrict__ C_dual, int ldc,
    int Ndim, int Kdim, int relu)
{
    constexpr int WN = (BM == 128) ? 2 : 4;   // warps along n
    constexpr int CP = 128 / WN;              // cols per warp (64 / 32)
    constexpr int NP = CP / 16;               // 16-col pairs per warp (4 / 2)

    __shared__ __align__(16) __nv_bfloat16 Ah[BM][40];
    __shared__ __align__(16) __nv_bfloat16 Am[BM][40];
    __shared__ __align__(16) __nv_bfloat16 Bh[32][136];
    __shared__ __align__(16) __nv_bfloat16 Bm[32][136];
    __shared__ int rows0[BM], rows1[BM];

    const int tid = threadIdx.x;
    const int lane = tid & 31;
    const int wid = tid >> 5;
    const int warp_m = wid / WN;
    const int warp_n = wid % WN;
    const int row0 = blockIdx.y * BM;
    const int col0 = blockIdx.x * 128;

    const int* g0 = r0a;
    const int* g1 = r1a;
    float* Cout = C;
    if (blockIdx.z == 1) { g0 = r1a; g1 = r0a; Cout = C_dual; }

    if (tid < BM) {
        rows0[tid] = g0 ? __ldg(&g0[row0 + tid]) : (row0 + tid);
        rows1[tid] = g1 ? __ldg(&g1[row0 + tid]) : (row0 + tid);
    }
    __syncthreads();

    float acc[2][NP * 2][4];
#pragma unroll
    for (int i = 0; i < 2; i++)
#pragma unroll
        for (int j = 0; j < NP * 2; j++)
#pragma unroll
            for (int l = 0; l < 4; l++) acc[i][j][l] = 0.f;

    for (int k0 = 0; k0 < Kdim; k0 += 32) {
        const float* Ap; int lda; const int* rs; int kloc;
        if (k0 < kb1) { Ap = A0; lda = lda0; rs = rows0; kloc = k0; }
        else { Ap = A1; lda = lda1; rs = rows1; kloc = k0 - kb1; }

#pragma unroll
        for (int u = 0; u < BM / 32; u++) {
            int idx = tid + u * 256;
            int m = idx >> 3;
            int kq = (idx & 7) << 2;
            float4 v = *(const float4*)(Ap + (size_t)rs[m] * lda + kloc + kq);
            split_store4(&Ah[m][kq], &Am[m][kq], v);
        }
#pragma unroll
        for (int u = 0; u < 4; u++) {
            int idx = tid + u * 256;
            int kk = idx >> 5;
            int nq = (idx & 31) << 2;
            float4 v = *(const float4*)(B + (size_t)(k0 + kk) * Ndim + col0 + nq);
            split_store4(&Bh[kk][nq], &Bm[kk][nq], v);
        }
        __syncthreads();

#pragma unroll
        for (int h = 0; h < 2; h++) {
            const int kh = h * 16;
            uint32_t ah[2][4], am[2][4];
#pragma unroll
            for (int mt = 0; mt < 2; mt++) {
                int r = warp_m * 32 + mt * 16 + (lane & 15);
                int kc = kh + ((lane >> 4) << 3);
                uint32_t addr = s2u(&Ah[r][kc]);
                LDSM4(ah[mt][0], ah[mt][1], ah[mt][2], ah[mt][3], addr);
                addr = s2u(&Am[r][kc]);
                LDSM4(am[mt][0], am[mt][1], am[mt][2], am[mt][3], addr);
            }
#pragma unroll
            for (int p = 0; p < NP; p++) {
                uint32_t bh[4], bm[4];
                int kr = kh + (lane & 15);
                int cb = warp_n * CP + p * 16 + ((lane >> 4) << 3);
                uint32_t addr = s2u(&Bh[kr][cb]);
                LDSM4T(bh[0], bh[1], bh[2], bh[3], addr);
                addr = s2u(&Bm[kr][cb]);
                LDSM4T(bm[0], bm[1], bm[2], bm[3], addr);
#pragma unroll
                for (int mt = 0; mt < 2; mt++) {
                    MMA16816(acc[mt][p * 2 + 0], ah[mt], bh[0], bh[1]);
                    MMA16816(acc[mt][p * 2 + 0], ah[mt], bm[0], bm[1]);
                    MMA16816(acc[mt][p * 2 + 0], am[mt], bh[0], bh[1]);
                    MMA16816(acc[mt][p * 2 + 1], ah[mt], bh[2], bh[3]);
                    MMA16816(acc[mt][p * 2 + 1], ah[mt], bm[2], bm[3]);
                    MMA16816(acc[mt][p * 2 + 1], am[mt], bh[2], bh[3]);
                }
            }
        }
        __syncthreads();
    }

    const int rbase = row0 + warp_m * 32 + (lane >> 2);
    const int cbase = col0 + warp_n * CP + (lane & 3) * 2;
#pragma unroll
    for (int mt = 0; mt < 2; mt++) {
#pragma unroll
        for (int hf = 0; hf < 2; hf++) {
            int r = rbase + mt * 16 + hf * 8;
            float* crow = Cout + (size_t)r * ldc;
            const float* cinr = Cin ? (Cin + (size_t)r * ldcin) : nullptr;
#pragma unroll
            for (int nt = 0; nt < NP * 2; nt++) {
                int c = cbase + nt * 8;
                float v0 = acc[mt][nt][hf * 2 + 0];
                float v1 = acc[mt][nt][hf * 2 + 1];
                if (bias) { v0 += __ldg(&bias[c]); v1 += __ldg(&bias[c + 1]); }
                if (cinr) { v0 += cs * cinr[c]; v1 += cs * cinr[c + 1]; }
                if (relu) { v0 = fmaxf(v0, 0.f); v1 = fmaxf(v1, 0.f); }
                crow[c] = v0;
                crow[c + 1] = v1;
            }
        }
    }
}

// =====================================================================
// trans_apply_mma: store rows = plan(^T) @ feats, bf16-split tensor cores.
// grid (ncols/128, rowtiles64, NGRP); z = 2*b + mode.
// mode 0: out grp 2b = P @ F(grp 2b+1); mode 1: out grp 2b+1 = P^T @ F(grp 2b).
// padK: K loop bound (multiple of 32, <= maxr); F rows >= nreal read as 0.
// =====================================================================
__global__ __launch_bounds__(256) void trans_apply_mma(
    const float* __restrict__ plan, const float* __restrict__ upd,
    float* __restrict__ store, int maxr, int nreal, int ld, int coff, int padK)
{
    __shared__ __align__(16) __nv_bfloat16 Ah[64][40];
    __shared__ __align__(16) __nv_bfloat16 Am[64][40];
    __shared__ __align__(16) __nv_bfloat16 Bh[32][136];
    __shared__ __align__(16) __nv_bfloat16 Bm[32][136];

    const int tid = threadIdx.x;
    const int lane = tid & 31;
    const int wid = tid >> 5;
    const int warp_m = wid >> 2;   // 0..1
    const int warp_n = wid & 3;    // 0..3
    const int z = blockIdx.z;
    const int b = z >> 1;
    const int mode = z & 1;
    const float* P = plan + (size_t)b * maxr * maxr;
    const int fgrp = 2 * b + (mode ? 0 : 1);
    const int ogrp = 2 * b + mode;
    const float* F = upd + (size_t)fgrp * nreal * ld + coff;
    float* C = store + (size_t)ogrp * nreal * ld + coff;
    const int row0 = blockIdx.y * 64;
    const int col0 = blockIdx.x * 128;

    float acc[2][4][4];
#pragma unroll
    for (int i = 0; i < 2; i++)
#pragma unroll
        for (int j = 0; j < 4; j++)
#pragma unroll
            for (int l = 0; l < 4; l++) acc[i][j][l] = 0.f;

    for (int k0 = 0; k0 < padK; k0 += 32) {
        if (mode == 0) {
#pragma unroll
            for (int u = 0; u < 2; u++) {
                int idx = tid + u * 256;
                int r = idx >> 3;
                int kq = (idx & 7) << 2;
                float4 v = *(const float4*)(P + (size_t)(row0 + r) * maxr + k0 + kq);
                split_store4(&Ah[r][kq], &Am[r][kq], v);
            }
        } else {
#pragma unroll
            for (int u = 0; u < 8; u++) {
                int idx = tid + u * 256;
                int r = idx & 63;
                int kk = idx >> 6;
                float v = P[(size_t)(k0 + kk) * maxr + row0 + r];
                __nv_bfloat16 h = __float2bfloat16(v);
                Ah[r][kk] = h;
                Am[r][kk] = __float2bfloat16(v - __bfloat162float(h));
            }
        }
#pragma unroll
        for (int u = 0; u < 4; u++) {
            int idx = tid + u * 256;
            int kk = idx >> 5;
            int nq = (idx & 31) << 2;
            int gk = k0 + kk;
            float4 v = make_float4(0.f, 0.f, 0.f, 0.f);
            if (gk < nreal) v = *(const float4*)(F + (size_t)gk * ld + col0 + nq);
            split_store4(&Bh[kk][nq], &Bm[kk][nq], v);
        }
        __syncthreads();

#pragma unroll
        for (int h = 0; h < 2; h++) {
            const int kh = h * 16;
            uint32_t ah[2][4], am[2][4];
#pragma unroll
            for (int mt = 0; mt < 2; mt++) {
                int r = warp_m * 32 + mt * 16 + (lane & 15);
                int kc = kh + ((lane >> 4) << 3);
                uint32_t addr = s2u(&Ah[r][kc]);
                LDSM4(ah[mt][0], ah[mt][1], ah[mt][2], ah[mt][3], addr);
                addr = s2u(&Am[r][kc]);
                LDSM4(am[mt][0], am[mt][1], am[mt][2], am[mt][3], addr);
            }
#pragma unroll
            for (int p = 0; p < 2; p++) {
                uint32_t bh[4], bm[4];
                int kr = kh + (lane & 15);
                int cb = warp_n * 32 + p * 16 + ((lane >> 4) << 3);
                uint32_t addr = s2u(&Bh[kr][cb]);
                LDSM4T(bh[0], bh[1], bh[2], bh[3], addr);
                addr = s2u(&Bm[kr][cb]);
                LDSM4T(bm[0], bm[1], bm[2], bm[3], addr);
#pragma unroll
                for (int mt = 0; mt < 2; mt++) {
                    MMA16816(acc[mt][p * 2 + 0], ah[mt], bh[0], bh[1]);
                    MMA16816(acc[mt][p * 2 + 0], ah[mt], bm[0], bm[1]);
                    MMA16816(acc[mt][p * 2 + 0], am[mt], bh[0], bh[1]);
                    MMA16816(acc[mt][p * 2 + 1], ah[mt], bh[2], bh[3]);
                    MMA16816(acc[mt][p * 2 + 1], ah[mt], bm[2], bm[3]);
                    MMA16816(acc[mt][p * 2 + 1], am[mt], bh[2], bh[3]);
                }
            }
        }
        __syncthreads();
    }

    const int rbase = row0 + warp_m * 32 + (lane >> 2);
    const int cbase = col0 + warp_n * 32 + (lane & 3) * 2;
#pragma unroll
    for (int mt = 0; mt < 2; mt++) {
#pragma unroll
        for (int hf = 0; hf < 2; hf++) {
            int r = rbase + mt * 16 + hf * 8;
            if (r >= nreal) continue;
            float* crow = C + (size_t)r * ld;
#pragma unroll
            for (int nt = 0; nt < 4; nt++) {
                int c = cbase + nt * 8;
                crow[c] = acc[mt][nt][hf * 2 + 0];
                crow[c + 1] = acc[mt][nt][hf * 2 + 1];
            }
        }
    }
}

// ---------------- misc elementwise ----------------
__global__ void zero_kernel(float* __restrict__ p, size_t n) {
    size_t i = (size_t)blockIdx.x * blockDim.x + threadIdx.x;
    size_t stride = (size_t)gridDim.x * blockDim.x;
    for (; i < n; i += stride) p[i] = 0.f;
}

__global__ void wab_kernel(const float* __restrict__ msgW, float* __restrict__ wab) {
    int i = blockIdx.x * blockDim.x + threadIdx.x;
    if (i < 128 * 256) wab[i] = msgW[i] + msgW[128 * 256 + i];
}

// sumsd[e][0:128] = hn[from[e]] + hn[to[e]]  (hn stride 768), float4
__global__ void sumsd_kernel(const float* __restrict__ hn, const int* __restrict__ from_idx,
                             const int* __restrict__ to_idx, float* __restrict__ out)
{
    int i = blockIdx.x * blockDim.x + threadIdx.x;
    if (i >= VE * 32) return;
    int e = i >> 5;
    int c4 = (i & 31) << 2;
    const float4 a = *(const float4*)(hn + (size_t)from_idx[e] * 768 + c4);
    const float4 b = *(const float4*)(hn + (size_t)to_idx[e] * 768 + c4);
    float4 o;
    o.x = a.x + b.x; o.y = a.y + b.y; o.z = a.z + b.z; o.w = a.w + b.w;
    *(float4*)(out + (size_t)e * 128 + c4) = o;
}

// ---------------- CSR build (once per launch) ----------------
__global__ void count_deg_kernel(const int* __restrict__ from_idx, const int* __restrict__ to_idx,
                                 int* __restrict__ deg)
{
    int e = blockIdx.x * blockDim.x + threadIdx.x;
    if (e >= VE) return;
    atomicAdd(&deg[to_idx[e]], 1);
    atomicAdd(&deg[from_idx[e]], 1);
}

__global__ __launch_bounds__(256) void scan_kernel(const int* __restrict__ deg,
                                                   int* __restrict__ off, int* __restrict__ pos)
{
    __shared__ int part[256];
    int t = threadIdx.x;
    int base = t * 24;
    int local[24];
    int s = 0;
#pragma unroll
    for (int i = 0; i < 24; i++) {
        local[i] = s;
        s += deg[base + i];
    }
    part[t] = s;
    __syncthreads();
    if (t == 0) {
        int acc = 0;
        for (int i = 0; i < 256; i++) { int v = part[i]; part[i] = acc; acc += v; }
    }
    __syncthreads();
    int o = part[t];
#pragma unroll
    for (int i = 0; i < 24; i++) {
        off[base + i] = o + local[i];
        pos[base + i] = o + local[i];
    }
    if (t == 255) off[VN] = o + s;
}

__global__ void fill_csr_kernel(const int* __restrict__ from_idx, const int* __restrict__ to_idx,
                                int* __restrict__ pos, int* __restrict__ list)
{
    int e = blockIdx.x * blockDim.x + threadIdx.x;
    if (e >= VE) return;
    int i = atomicAdd(&pos[to_idx[e]], 1);
    list[i] = 2 * e;
    i = atomicAdd(&pos[from_idx[e]], 1);
    list[i] = 2 * e + 1;
}

// agg[n] = sum over incident entries: even -> fwd[e], odd -> bwd[e]
__global__ __launch_bounds__(256) void agg_gather_kernel(
    const float* __restrict__ fwd, const float* __restrict__ bwd,
    const int* __restrict__ off, const int* __restrict__ list,
    float* __restrict__ agg)
{
    int n = blockIdx.x;
    int c = threadIdx.x;
    int s0 = off[n], s1 = off[n + 1];
    float s = 0.f;
    for (int j = s0; j < s1; j++) {
        int ent = __ldg(&list[j]);
        const float* src = (ent & 1) ? bwd : fwd;
        s += src[(size_t)(ent >> 1) * 256 + c];
    }
    agg[(size_t)n * 256 + c] = s;
}

// ---------------- transport MLP: 8 rows/block (fdim -> 64 -> 64) ----------------
__global__ __launch_bounds__(64) void transport_mlp8_kernel(
    const float* __restrict__ upd, int ld, int foff, int fdim,
    const float* __restrict__ W1, const float* __restrict__ b1,
    const float* __restrict__ W2, const float* __restrict__ b2,
    float* __restrict__ tout, int maxr, int nreal)
{
    __shared__ float f[8][257];
    __shared__ float hid[8][65];
    int i0 = blockIdx.x * 8;
    int g = blockIdx.y;
    int j = threadIdx.x;

    for (int r = 0; r < 8; r++) {
        int row = i0 + r;
        if (row < nreal) {
            const float* frow = upd + ((size_t)g * nreal + row) * ld + foff;
            for (int k = j; k < fdim; k += 64) f[r][k] = frow[k];
        }
    }
    __syncthreads();

    float h[8];
#pragma unroll
    for (int r = 0; r < 8; r++) h[r] = b1[j];
    for (int k = 0; k < fdim; k++) {
        float w = W1[k * 64 + j];
#pragma unroll
        for (int r = 0; r < 8; r++) h[r] += f[r][k] * w;
    }
#pragma unroll
    for (int r = 0; r < 8; r++) hid[r][j] = fmaxf(h[r], 0.f);
    __syncthreads();

    float o[8];
#pragma unroll
    for (int r = 0; r < 8; r++) o[r] = b2[j];
    for (int k = 0; k < 64; k++) {
        float w = W2[k * 64 + j];
#pragma unroll
        for (int r = 0; r < 8; r++) o[r] += hid[r][k] * w;
    }
#pragma unroll
    for (int r = 0; r < 8; r++) {
        int row = i0 + r;
        tout[((size_t)g * maxr + row) * 64 + j] = (row < nreal) ? o[r] : 0.f;
    }
}

// ---------------- la = (tq @ tc^T) / TEMP ----------------
__global__ void la_kernel(const float* __restrict__ t, float* __restrict__ la, int maxr)
{
    __shared__ float Tq[16][65];
    __shared__ float Tc[16][65];
    int b = blockIdx.z;
    int q0 = blockIdx.y * 16;
    int c0 = blockIdx.x * 16;
    const float* tq = t + (size_t)(2 * b) * maxr * 64;
    const float* tc = t + (size_t)(2 * b + 1) * maxr * 64;
    int ty = threadIdx.y, tx = threadIdx.x;
    int lin = ty * 16 + tx;
#pragma unroll
    for (int u = 0; u < 4; u++) {
        int idx = lin + u * 256;
        int r = idx / 64, k = idx % 64;
        Tq[r][k] = tq[(size_t)(q0 + r) * 64 + k];
        Tc[r][k] = tc[(size_t)(c0 + r) * 64 + k];
    }
    __syncthreads();
    float s = 0.f;
#pragma unroll
    for (int k = 0; k < 64; k++) s += Tq[ty][k] * Tc[tx][k];
    la[((size_t)b * maxr + q0 + ty) * maxr + c0 + tx] = s * INV_TEMP;
}

// ---------------- fused node Sinkhorn: smem-resident 64x64, 10 iters + exp
__global__ __launch_bounds__(256) void node_sink_kernel(float* __restrict__ la)
{
    __shared__ float L[64][65];
    float* base = la + (size_t)blockIdx.x * 4096;
    int tid = threadIdx.x;
    for (int i = tid; i < 4096; i += 256) L[i >> 6][i & 63] = base[i];
    __syncthreads();
    int r = tid >> 2;
    int part = (tid & 3) * 16;
    for (int iter = 0; iter < SINK_ITERS; iter++) {
        {
            float m = -INFINITY;
#pragma unroll
            for (int i = 0; i < 16; i++) m = fmaxf(m, L[r][part + i]);
            m = fmaxf(m, __shfl_xor_sync(0xFFFFFFFFu, m, 1));
            m = fmaxf(m, __shfl_xor_sync(0xFFFFFFFFu, m, 2));
            float s = 0.f;
#pragma unroll
            for (int i = 0; i < 16; i++) s += expf(L[r][part + i] - m);
            s += __shfl_xor_sync(0xFFFFFFFFu, s, 1);
            s += __shfl_xor_sync(0xFFFFFFFFu, s, 2);
            float lse = m + logf(s);
#pragma unroll
            for (int i = 0; i < 16; i++) L[r][part + i] -= lse;
        }
        __syncthreads();
        {
            float m = -INFINITY;
#pragma unroll
            for (int i = 0; i < 16; i++) m = fmaxf(m, L[part + i][r]);
            m = fmaxf(m, __shfl_xor_sync(0xFFFFFFFFu, m, 1));
            m = fmaxf(m, __shfl_xor_sync(0xFFFFFFFFu, m, 2));
            float s = 0.f;
#pragma unroll
            for (int i = 0; i < 16; i++) s += expf(L[part + i][r] - m);
            s += __shfl_xor_sync(0xFFFFFFFFu, s, 1);
            s += __shfl_xor_sync(0xFFFFFFFFu, s, 2);
            float lse = m + logf(s);
#pragma unroll
            for (int i = 0; i < 16; i++) L[part + i][r] -= lse;
        }
        __syncthreads();
    }
    for (int i = tid; i < 4096; i += 256) base[i] = expf(L[i >> 6][i & 63]);
}

// ---------------- fused edge Sinkhorn: 256x256, 10 iters + exp
__global__ __launch_bounds__(1024) void edge_sink_kernel(float* __restrict__ la)
{
    float* base = la + (size_t)blockIdx.x * 65536;
    int tid = threadIdx.x;
    int wid = tid >> 5, lane = tid & 31;
    __shared__ float cr[4][256];
    int c = tid & 255, g = tid >> 8;
    for (int iter = 0; iter < SINK_ITERS; iter++) {
        for (int r = wid; r < 256; r += 32) {
            float* rp = base + (size_t)r * 256;
            float4 v0 = *(float4*)(rp + lane * 4);
            float4 v1 = *(float4*)(rp + 128 + lane * 4);
            float m = fmaxf(fmaxf(fmaxf(v0.x, v0.y), fmaxf(v0.z, v0.w)),
                            fmaxf(fmaxf(v1.x, v1.y), fmaxf(v1.z, v1.w)));
#pragma unroll
            for (int o = 16; o > 0; o >>= 1) m = fmaxf(m, __shfl_xor_sync(0xFFFFFFFFu, m, o));
            float s = expf(v0.x - m) + expf(v0.y - m) + expf(v0.z - m) + expf(v0.w - m)
                    + expf(v1.x - m) + expf(v1.y - m) + expf(v1.z - m) + expf(v1.w - m);
#pragma unroll
            for (int o = 16; o > 0; o >>= 1) s += __shfl_xor_sync(0xFFFFFFFFu, s, o);
            float lse = m + logf(s);
            v0.x -= lse; v0.y -= lse; v0.z -= lse; v0.w -= lse;
            v1.x -= lse; v1.y -= lse; v1.z -= lse; v1.w -= lse;
            *(float4*)(rp + lane * 4) = v0;
            *(float4*)(rp + 128 + lane * 4) = v1;
        }
        __syncthreads();
        float m = -INFINITY;
        for (int r = g * 64; r < g * 64 + 64; r++) m = fmaxf(m, base[(size_t)r * 256 + c]);
        cr[g][c] = m;
        __syncthreads();
        if (g == 0) cr[0][c] = fmaxf(fmaxf(cr[0][c], cr[1][c]), fmaxf(cr[2][c], cr[3][c]));
        __syncthreads();
        m = cr[0][c];
        float s = 0.f;
        for (int r = g * 64; r < g * 64 + 64; r++) s += expf(base[(size_t)r * 256 + c] - m);
        __syncthreads();
        cr[g][c] = s;
        __syncthreads();
        if (g == 0) cr[0][c] = m + logf(cr[0][c] + cr[1][c] + cr[2][c] + cr[3][c]);
        __syncthreads();
        float lse = cr[0][c];
        bool last = (iter == SINK_ITERS - 1);
        for (int r = g * 64; r < g * 64 + 64; r++) {
            float v = base[(size_t)r * 256 + c] - lse;
            base[(size_t)r * 256 + c] = last ? expf(v) : v;
        }
        __syncthreads();
    }
}

// ---------------- score ----------------
__global__ void score_kernel(const float* __restrict__ upd_node, const float* __restrict__ plan,
                             float* __restrict__ out)
{
    int b = blockIdx.x;
    int t = threadIdx.x;
    __shared__ float P[64][64];
    __shared__ float FC[48][128];
    __shared__ float red[128];
    for (int idx = t; idx < 64 * 64; idx += 128)
        P[idx / 64][idx % 64] = plan[(size_t)b * 4096 + idx];
    for (int idx = t; idx < 48 * 128; idx += 128) {
        int c = idx / 128, d = idx % 128;
        FC[c][d] = upd_node[((size_t)(2 * b + 1) * 48 + c) * 768 + 640 + d];
    }
    __syncthreads();
    float acc = 0.f;
    for (int q = 0; q < 64; q++) {
        float s = 0.f;
#pragma unroll 8
        for (int c = 0; c < 48; c++) s += P[q][c] * FC[c][t];
        float fq = 0.f;
        if (q < 48) fq = upd_node[((size_t)(2 * b) * 48 + q) * 768 + 640 + t];
        acc += fmaxf(fq - s, 0.f);
    }
    red[t] = acc;
    __syncthreads();
    for (int s2 = 64; s2 > 0; s2 >>= 1) {
        if (t < s2) red[t] += red[t + s2];
        __syncthreads();
    }
    if (t == 0) out[b] = -red[0];
}

// ---------------- host helpers ----------------
struct Seg { const float* A; int lda; const int* rows; };

static void bgemmE(Seg s0, Seg s1, int kb1, const float* B, const float* bias,
                   const float* Cin, int ldcin, float cs,
                   float* C, float* Cd, int ldc, int M, int N, int K, int relu, int dual)
{
    dim3 g(N / 128, M / 128, dual ? 2 : 1);
    bgemm_kernel<128><<<g, 256>>>(s0.A, s0.lda, s0.rows, s1.A, s1.lda, s1.rows, kb1,
                                  B, bias, Cin, ldcin, cs, C, Cd, ldc, N, K, relu);
}

static void bgemmN(Seg s0, Seg s1, int kb1, const float* B, const float* bias,
                   const float* Cin, int ldcin, float cs,
                   float* C, int ldc, int M, int N, int K, int relu)
{
    dim3 g(N / 128, M / 64, 1);
    bgemm_kernel<64><<<g, 256>>>(s0.A, s0.lda, s0.rows, s1.A, s1.lda, s1.rows, kb1,
                                 B, bias, Cin, ldcin, cs, C, nullptr, ldc, N, K, relu);
}

static void zero_buf(float* p, size_t n)
{
    int grid = (int)((n + 255) / 256);
    if (grid > 8192) grid = 8192;
    zero_kernel<<<grid, 256>>>(p, n);
}

extern "C" void kernel_launch(void* const* d_in, const int* in_sizes, int n_in,
                              void* d_out, int out_size)
{
    const float* node_features = (const float*)d_in[0];
    const float* edge_features = (const float*)d_in[1];
    const int* from_idx = (const int*)d_in[2];
    const int* to_idx = (const int*)d_in[3];
    const float* enc_node_W = (const float*)d_in[4];
    const float* enc_node_b = (const float*)d_in[5];
    const float* enc_edge_W = (const float*)d_in[6];
    const float* enc_edge_b = (const float*)d_in[7];
    const float* ni_W1 = (const float*)d_in[8];
    const float* ni_b1 = (const float*)d_in[9];
    const float* ni_W2 = (const float*)d_in[10];
    const float* ni_b2 = (const float*)d_in[11];
    const float* ei_W1 = (const float*)d_in[12];
    const float* ei_b1 = (const float*)d_in[13];
    const float* ei_W2 = (const float*)d_in[14];
    const float* ei_b2 = (const float*)d_in[15];
    const float* msg_W = (const float*)d_in[16];
    const float* msg_b = (const float*)d_in[17];
    const float* nu_W1 = (const float*)d_in[18];
    const float* nu_b1 = (const float*)d_in[19];
    const float* nu_W2 = (const float*)d_in[20];
    const float* nu_b2 = (const float*)d_in[21];
    const float* ns_W1 = (const float*)d_in[22];
    const float* ns_b1 = (const float*)d_in[23];
    const float* ns_W2 = (const float*)d_in[24];
    const float* ns_b2 = (const float*)d_in[25];
    const float* es_W1 = (const float*)d_in[26];
    const float* es_b1 = (const float*)d_in[27];
    const float* es_W2 = (const float*)d_in[28];
    const float* es_b2 = (const float*)d_in[29];

    float* S = nullptr;
    cudaGetSymbolAddress((void**)&S, g_scratch);

    float* enc_n = S + OFF_ENC_N;
    float* enc_e = S + OFF_ENC_E;
    float* node_store = S + OFF_NS;
    float* edge_store = S + OFF_ES;
    float* UN = S + OFF_UN;
    float* UE = S + OFF_UE;
    float* tmpN = S + OFF_TMPN;
    float* tmpE = S + OFF_TMPE;
    float* hcomb = S + OFF_HC;
    float* ecomb = S + OFF_EC;
    float* fwd = S + OFF_FWD;
    float* bwd = S + OFF_BWD;
    float* agg = S + OFF_AGG;
    float* TN = S + OFF_TN;
    float* TE = S + OFF_TE;
    float* PLN = S + OFF_PLN;
    float* PLE = S + OFF_PLE;
    float* ewc = S + OFF_EWC;
    float* wab = S + OFF_WAB;
    int* csr = (int*)(S + OFF_CSR);
    int* deg = csr;                 // VN
    int* off = csr + VN;            // VN+1
    int* pos = off + VN + 1;        // VN
    int* list = pos + VN;           // 2*VE

    Seg none{nullptr, 0, nullptr};

    // one-time zeroing + precompute
    zero_buf(node_store, SZ_NS);
    zero_buf(edge_store, SZ_ES);
    zero_buf((float*)deg, VN);
    wab_kernel<<<(128 * 256 + 255) / 256, 256>>>(msg_W, wab);
    count_deg_kernel<<<(VE + 255) / 256, 256>>>(from_idx, to_idx, deg);
    scan_kernel<<<1, 256>>>(deg, off, pos);
    fill_csr_kernel<<<(VE + 255) / 256, 256>>>(from_idx, to_idx, pos, list);

    // encoders (K=32)
    bgemmN(Seg{node_features, DIN, nullptr}, none, 32,
           enc_node_W, enc_node_b, nullptr, 0, 0.f, enc_n, 128, VN, 128, 32, 0);
    bgemmE(Seg{edge_features, DIN, nullptr}, none, 32,
           enc_edge_W, enc_edge_b, nullptr, 0, 0.f, enc_e, nullptr, 128, VE, 128, 32, 0, 0);

    for (int k = 0; k < KK; k++) {
        for (int p = 1; p <= TT; p++) {
            const float* hptr = (p == 1) ? enc_n : (UN + (size_t)(p - 1) * 128);
            int hlda = (p == 1) ? 128 : 768;

            // h_comb = mlp2([h | node_store slice], ni)
            bgemmN(Seg{hptr, hlda, nullptr},
                   Seg{node_store + (size_t)(p - 1) * 128, 768, nullptr}, 128,
                   ni_W1, ni_b1, nullptr, 0, 0.f, tmpN, 256, VN, 256, 256, 1);
            bgemmN(Seg{tmpN, 256, nullptr}, none, 256,
                   ni_W2, ni_b2, nullptr, 0, 0.f, hcomb, 128, VN, 128, 256, 0);

            // e_comb = mlp2([enc_e | edge_store slice], ei)
            bgemmE(Seg{enc_e, 128, nullptr},
                   Seg{edge_store + (size_t)(p - 1) * 256, 1536, nullptr}, 128,
                   ei_W1, ei_b1, nullptr, 0, 0.f, tmpE, nullptr, 384, VE, 384, 384, 1, 0);
            bgemmE(Seg{tmpE, 384, nullptr}, none, 384,
                   ei_W2, ei_b2, nullptr, 0, 0.f, ecomb, nullptr, 128, VE, 128, 384, 0, 0);

            // EWc = ecomb @ msg_W[256:384] + msg_b
            bgemmE(Seg{ecomb, 128, nullptr}, none, 128,
                   msg_W + 256 * 256, msg_b, nullptr, 0, 0.f, ewc, nullptr, 256, VE, 256, 128, 0, 0);

            // fwd & bwd in ONE dual launch
            bgemmE(Seg{hcomb, 128, from_idx}, Seg{hcomb, 128, to_idx}, 128,
                   msg_W, nullptr, ewc, 256, 1.f, fwd, bwd, 256, VE, 256, 256, 0, 1);

            // aggregate via CSR gather (no atomics)
            agg_gather_kernel<<<VN, 256>>>(fwd, bwd, off, list, agg);

            // h_new = mlp2([h_comb | agg], nu) -> UN slot p
            bgemmN(Seg{hcomb, 128, nullptr}, Seg{agg, 256, nullptr}, 128,
                   nu_W1, nu_b1, nullptr, 0, 0.f, tmpN, 256, VN, 256, 384, 1);
            bgemmN(Seg{tmpN, 256, nullptr}, none, 256,
                   nu_W2, nu_b2, nullptr, 0, 0.f, UN + (size_t)p * 128, 768, VN, 128, 256, 0);

            // msgs2 = (h[from]+h[to]) @ (Wa+Wb) + 2*EWc -> UE slot p
            const float* hn = UN + (size_t)p * 128;
            sumsd_kernel<<<(VE * 32 + 255) / 256, 256>>>(hn, from_idx, to_idx, tmpE);
            bgemmE(Seg{tmpE, 128, nullptr}, none, 128,
                   wab, nullptr, ewc, 256, 2.f, UE + (size_t)p * 256, nullptr, 1536, VE, 256, 128, 0, 0);
        }

        // ----- node transport -----
        transport_mlp8_kernel<<<dim3(MAXN / 8, NGRP), 64>>>(UN, 768, 640, 128, ns_W1, ns_b1,
                                                            ns_W2, ns_b2, TN, MAXN, NPER);
        la_kernel<<<dim3(4, 4, BNUM), dim3(16, 16)>>>(TN, PLN, MAXN);
        node_sink_kernel<<<BNUM, 256>>>(PLN);
        trans_apply_mma<<<dim3(5, 1, NGRP), 256>>>(PLN, UN, node_store, MAXN, NPER, 768, 128, 64);

        // ----- edge transport -----
        transport_mlp8_kernel<<<dim3(MAXE / 8, NGRP), 64>>>(UE, 1536, 1280, 256, es_W1, es_b1,
                                                            es_W2, es_b2, TE, MAXE, EPER);
        la_kernel<<<dim3(16, 16, BNUM), dim3(16, 16)>>>(TE, PLE, MAXE);
        edge_sink_kernel<<<BNUM, 1024>>>(PLE);
        trans_apply_mma<<<dim3(10, 3, NGRP), 256>>>(PLE, UE, edge_store, MAXE, EPER, 1536, 256, 192);
    }

    // ----- score -----
    score_kernel<<<BNUM, 128>>>(UN, PLN, (float*)d_out);
}